// round 7
// baseline (speedup 1.0000x reference)
#include <cuda_runtime.h>
#include <cuda_fp16.h>
#include <math.h>
#include <stdint.h>

#define BATCH 768
#define NS 32
#define NP 24
#define EDIM 64
#define HDIM 128
#define G4 512      // 4*HDIM
#define P1D 512     // pool hidden
#define BNK 1024
#define MLPD 1024
#define KTOT (HDIM + BNK)   // 1152
#define TSTEPS 12
#define KC 16

// ---------------- scratch (static device memory; no allocations) ----------------
__device__ float g_pos[BATCH * 2];
__device__ float g_decin[BATCH * EDIM];
__device__ float g_h[BATCH * HDIM];
__device__ float g_c[BATCH * HDIM];
__device__ float g_hmid[BATCH * HDIM];
__device__ float g_hterm[BATCH * P1D];
__device__ __half g_y[(size_t)BATCH * NP * P1D];   // fp16
__device__ float g_pool[(size_t)BATCH * BNK];
__device__ float g_dh[(size_t)BATCH * MLPD];
__device__ float g_M2[2 * P1D];
__device__ float g_cb[P1D];
__device__ __half g_Wp2t[(size_t)BNK * P1D];       // W_p2^T fp16
__device__ __half g_Wm1t[(size_t)MLPD * KTOT];     // W_m1^T fp16

__device__ __forceinline__ float sigf(float x) { return 1.f / (1.f + expf(-x)); }

// warp-level fp16 HMMA (generic PTX, sm_80+): m16n8k16, fp32 accum
__device__ __forceinline__ void mma_f16(float* d, const uint32_t* a, const uint32_t* b) {
    asm volatile(
        "mma.sync.aligned.m16n8k16.row.col.f32.f16.f16.f32 "
        "{%0,%1,%2,%3}, {%4,%5,%6,%7}, {%8,%9}, {%0,%1,%2,%3};"
        : "+f"(d[0]), "+f"(d[1]), "+f"(d[2]), "+f"(d[3])
        : "r"(a[0]), "r"(a[1]), "r"(a[2]), "r"(a[3]), "r"(b[0]), "r"(b[1]));
}

__device__ __forceinline__ void ldsm_x4(uint32_t* r, uint32_t saddr) {
    asm volatile("ldmatrix.sync.aligned.m8n8.x4.shared.b16 {%0,%1,%2,%3}, [%4];"
                 : "=r"(r[0]), "=r"(r[1]), "=r"(r[2]), "=r"(r[3]) : "r"(saddr));
}

__device__ __forceinline__ uint32_t smem_u32(const void* p) {
    uint32_t a;
    asm("{ .reg .u64 t; cvta.to.shared.u64 t, %1; cvt.u32.u64 %0, t; }" : "=r"(a) : "l"(p));
    return a;
}
__device__ __forceinline__ void cp_async16(uint32_t saddr, const void* g) {
    asm volatile("cp.async.cg.shared.global [%0], [%1], 16;" :: "r"(saddr), "l"(g));
}
#define CP_COMMIT() asm volatile("cp.async.commit_group;" ::: "memory")
#define CP_WAIT(n)  asm volatile("cp.async.wait_group %0;" :: "n"(n) : "memory")

// ---------------- setup ----------------
__global__ void setup_kernel(const float* __restrict__ last_pos,
                             const float* __restrict__ last_pos_rel,
                             const float* __restrict__ h0, const float* __restrict__ c0,
                             const float* __restrict__ W_se, const float* __restrict__ b_se,
                             const float* __restrict__ W_pse, const float* __restrict__ b_pse,
                             const float* __restrict__ W_p1, const float* __restrict__ b_p1,
                             const float* __restrict__ W_p2, const float* __restrict__ W_m1) {
    int tid = blockIdx.x * blockDim.x + threadIdx.x;
    int nt = gridDim.x * blockDim.x;
    for (int i = tid; i < BATCH * 2; i += nt) g_pos[i] = last_pos[i];
    for (int i = tid; i < BATCH * HDIM; i += nt) { g_h[i] = h0[i]; g_c[i] = c0[i]; }
    for (int i = tid; i < BATCH * EDIM; i += nt) {
        int b = i >> 6, e = i & 63;
        g_decin[i] = b_se[e] + last_pos_rel[b * 2] * W_se[e] + last_pos_rel[b * 2 + 1] * W_se[EDIM + e];
    }
    for (int i = tid; i < 2 * P1D; i += nt) {
        int d = i >> 9, t = i & 511;
        float a = 0.f;
        for (int e = 0; e < EDIM; e++) a += W_pse[d * EDIM + e] * W_p1[e * P1D + t];
        g_M2[i] = a;
    }
    for (int i = tid; i < P1D; i += nt) {
        float a = b_p1[i];
        for (int e = 0; e < EDIM; e++) a += b_pse[e] * W_p1[e * P1D + i];
        g_cb[i] = a;
    }
    for (int i = tid; i < BNK * P1D; i += nt) {
        int n = i / P1D, k = i % P1D;
        g_Wp2t[i] = __float2half_rn(W_p2[(size_t)k * BNK + n]);
    }
    for (int i = tid; i < MLPD * KTOT; i += nt) {
        int n = i / KTOT, k = i % KTOT;
        g_Wm1t[i] = __float2half_rn(W_m1[(size_t)k * MLPD + n]);
    }
}

// ---------------- fused LSTM step + hidden2pos + pos + dec_in + hterm ----------------
__global__ __launch_bounds__(512) void lstm_kernel(
    const float* __restrict__ W_ih, const float* __restrict__ b_ih,
    const float* __restrict__ W_hh, const float* __restrict__ b_hh,
    const float* __restrict__ W_hp, const float* __restrict__ b_hp,
    const float* __restrict__ W_se, const float* __restrict__ b_se,
    const float* __restrict__ W_p1,
    float* __restrict__ pred_out) {
    __shared__ float s_x[16 * EDIM];
    __shared__ float s_h[16 * HDIM];
    __shared__ float s_g[16 * G4];
    __shared__ float s_rel[32];
    int tid = threadIdx.x;
    int row0 = blockIdx.x * 16;
    for (int i = tid; i < 16 * EDIM; i += 512) s_x[i] = g_decin[row0 * EDIM + i];
    for (int i = tid; i < 16 * HDIM; i += 512) s_h[i] = g_h[row0 * HDIM + i];
    __syncthreads();
    {
        float acc[16];
        float bb = b_ih[tid] + b_hh[tid];
#pragma unroll
        for (int r = 0; r < 16; r++) acc[r] = bb;
        for (int k = 0; k < EDIM; k++) {
            float w = W_ih[k * G4 + tid];
#pragma unroll
            for (int r = 0; r < 16; r++) acc[r] += w * s_x[r * EDIM + k];
        }
        for (int k = 0; k < HDIM; k++) {
            float w = W_hh[k * G4 + tid];
#pragma unroll
            for (int r = 0; r < 16; r++) acc[r] += w * s_h[r * HDIM + k];
        }
#pragma unroll
        for (int r = 0; r < 16; r++) s_g[r * G4 + tid] = acc[r];
    }
    __syncthreads();
    for (int i = tid; i < 16 * HDIM; i += 512) {
        int r = i >> 7, hc = i & 127;
        const float* gr = s_g + r * G4;
        float ig = sigf(gr[hc]);
        float fg = sigf(gr[HDIM + hc]);
        float gg = tanhf(gr[2 * HDIM + hc]);
        float og = sigf(gr[3 * HDIM + hc]);
        float c = fg * g_c[(row0 + r) * HDIM + hc] + ig * gg;
        float hn = og * tanhf(c);
        g_c[(row0 + r) * HDIM + hc] = c;
        g_hmid[(row0 + r) * HDIM + hc] = hn;
        s_h[r * HDIM + hc] = hn;
    }
    __syncthreads();
    if (tid < 32) {
        int r = tid >> 1, d = tid & 1;
        float a = b_hp[d];
        for (int k = 0; k < HDIM; k++) a += s_h[r * HDIM + k] * W_hp[k * 2 + d];
        s_rel[tid] = a;
        pred_out[row0 * 2 + tid] = a;
        g_pos[row0 * 2 + tid] = a + g_pos[row0 * 2 + tid];
    }
    __syncthreads();
    for (int i = tid; i < 16 * EDIM; i += 512) {
        int r = i >> 6, e = i & 63;
        g_decin[(row0 + r) * EDIM + e] =
            b_se[e] + s_rel[r * 2] * W_se[e] + s_rel[r * 2 + 1] * W_se[EDIM + e];
    }
    // ---- fused hterm: hterm[row0+r][tid] = cb[tid] + sum_k h_new[r][k] * W_p1[64+k][tid]
    {
        float acc[16];
        float cb = g_cb[tid];
#pragma unroll
        for (int r = 0; r < 16; r++) acc[r] = cb;
        for (int k = 0; k < HDIM; k++) {
            float w = W_p1[(EDIM + k) * P1D + tid];
#pragma unroll
            for (int r = 0; r < 16; r++) acc[r] += w * s_h[r * HDIM + k];
        }
#pragma unroll
        for (int r = 0; r < 16; r++) g_hterm[(row0 + r) * P1D + tid] = acc[r];
    }
}

// ---------------- layer1: y = fp16(relu(hterm[j] + dx*M2[0] + dy*M2[1])); zero pool ----
__global__ __launch_bounds__(512) void layer1_kernel() {
    int s = blockIdx.x / NP, i = blockIdx.x % NP;
    int tid = threadIdx.x;
    __shared__ float sdx[NP], sdy[NP];
    if (tid < NP) {
        float xi = g_pos[(s * NP + i) * 2], yi = g_pos[(s * NP + i) * 2 + 1];
        sdx[tid] = g_pos[(s * NP + tid) * 2] - xi;
        sdy[tid] = g_pos[(s * NP + tid) * 2 + 1] - yi;
    }
    g_pool[(size_t)blockIdx.x * BNK + tid] = 0.f;
    g_pool[(size_t)blockIdx.x * BNK + P1D + tid] = 0.f;
    float m0 = g_M2[tid], m1 = g_M2[P1D + tid];
    __syncthreads();
    __half* yout = g_y + (size_t)blockIdx.x * NP * P1D;
#pragma unroll
    for (int j = 0; j < NP; j++) {
        float v = g_hterm[(s * NP + j) * P1D + tid] + sdx[j] * m0 + sdy[j] * m1;
        yout[j * P1D + tid] = __float2half_rn(fmaxf(v, 0.f));
    }
}

// ---------------- dominant GEMM: B-resident persistent CTA, fp16 mma + ldmatrix ---------
// grid (8, 18): n0 = bx*128; each CTA does 8 M-blocks of 128 rows with B[128n x 512k]
// resident in smem (128KB). A double-buffered 16KB chunks (128 rows x 64 halves),
// XOR-swizzled rows. Epilogue staged in fp16 (separate 34KB region).
#define SMB_B 0
#define SMB_A 131072
#define SMB_D 163840
#define SMEM_GP (163840 + 128 * 136 * 2)   // 198656
#define DP 136

__global__ __launch_bounds__(256) void gemm_pool_mma(const float* __restrict__ bp2) {
    extern __shared__ char smraw[];
    const uint32_t sb = smem_u32(smraw);
    const uint32_t sbB = sb + SMB_B;
    const uint32_t sbA = sb + SMB_A;
    __half* Dsm = (__half*)(smraw + SMB_D);
    const int tid = threadIdx.x;
    const int wid = tid >> 5, lane = tid & 31;
    const int gid = lane >> 2, tig = lane & 3;
    const int wm = (wid & 1) * 64, wn = (wid >> 1) * 32;
    const int n0 = blockIdx.x * 128;
    const int mb0 = blockIdx.y * 8;
    const int q = lane >> 3;
    const int mrow = (q & 1) * 8 + (lane & 7);
    const int mkof = (q >> 1) * 8;
    const uint32_t swz = (uint32_t)(lane & 7) << 4;

    // ---- one-time B fill (8192 cp.async) + A chunk0 prefetch, one commit group ----
    {
        const __half* Bg = g_Wp2t + (size_t)n0 * P1D;
#pragma unroll
        for (int p = 0; p < 32; p++) {
            int idx = tid + p * 256;
            int n = idx >> 6, seg = idx & 63;
            uint32_t dst = sbB + (uint32_t)n * 1024 + (((uint32_t)seg * 16) ^ ((uint32_t)(n & 7) << 4));
            cp_async16(dst, Bg + (size_t)n * P1D + seg * 8);
        }
        const __half* Ag = g_y + (size_t)mb0 * 128 * P1D;
#pragma unroll
        for (int p = 0; p < 4; p++) {
            int idx = tid + p * 256;
            int row = idx >> 3, seg = idx & 7;
            uint32_t dst = sbA + (uint32_t)row * 128 + (((uint32_t)seg * 16) ^ ((uint32_t)(row & 7) << 4));
            cp_async16(dst, Ag + (size_t)row * P1D + seg * 8);
        }
        CP_COMMIT();
    }

    int buf = 0;
    for (int t = 0; t < 8; t++) {
        const int R0 = (mb0 + t) * 128;
        float acc[4][4][4] = {};
        for (int ch = 0; ch < 8; ch++) {
            const int gc = t * 8 + ch + 1;     // next global chunk index
            if (gc < 64) {
                const int nt_ = gc >> 3, nc = gc & 7;
                const __half* src = g_y + (size_t)(mb0 + nt_) * 128 * P1D + nc * 64;
                uint32_t dstb = sbA + (uint32_t)(buf ^ 1) * 16384;
#pragma unroll
                for (int p = 0; p < 4; p++) {
                    int idx = tid + p * 256;
                    int row = idx >> 3, seg = idx & 7;
                    cp_async16(dstb + (uint32_t)row * 128 +
                                   (((uint32_t)seg * 16) ^ ((uint32_t)(row & 7) << 4)),
                               src + (size_t)row * P1D + seg * 8);
                }
                CP_COMMIT();
                CP_WAIT(1);
            } else {
                CP_WAIT(0);
            }
            __syncthreads();
            const uint32_t sA = sbA + (uint32_t)buf * 16384;
            const uint32_t kbB = (uint32_t)ch * 128;   // byte offset of this chunk in B rows
#pragma unroll
            for (int kk = 0; kk < 64; kk += 16) {
                const uint32_t kb = (uint32_t)(kk + mkof) * 2;
                uint32_t af[4][4], bf[4][2];
#pragma unroll
                for (int mi = 0; mi < 4; mi++) {
                    uint32_t addr = sA + (uint32_t)(wm + mi * 16 + mrow) * 128 + (kb ^ swz);
                    ldsm_x4(af[mi], addr);
                }
#pragma unroll
                for (int pi = 0; pi < 2; pi++) {
                    uint32_t r[4];
                    uint32_t addr = sbB + (uint32_t)(wn + pi * 16 + mrow) * 1024 + ((kbB + kb) ^ swz);
                    ldsm_x4(r, addr);
                    bf[2 * pi][0] = r[0]; bf[2 * pi][1] = r[2];
                    bf[2 * pi + 1][0] = r[1]; bf[2 * pi + 1][1] = r[3];
                }
#pragma unroll
                for (int mi = 0; mi < 4; mi++)
#pragma unroll
                    for (int ni = 0; ni < 4; ni++)
                        mma_f16(acc[mi][ni], af[mi], bf[ni]);
            }
            __syncthreads();
            buf ^= 1;
        }
        // ---- epilogue for m-block t: bias+relu -> fp16 stage, per-ped max, atomicMax ----
#pragma unroll
        for (int mi = 0; mi < 4; mi++)
#pragma unroll
            for (int ni = 0; ni < 4; ni++) {
                int r = wm + mi * 16 + gid;
                int c = wn + ni * 8 + 2 * tig;
                float bv0 = bp2[n0 + c], bv1 = bp2[n0 + c + 1];
                *(__half2*)(Dsm + r * DP + c) =
                    __floats2half2_rn(fmaxf(acc[mi][ni][0] + bv0, 0.f),
                                      fmaxf(acc[mi][ni][1] + bv1, 0.f));
                *(__half2*)(Dsm + (r + 8) * DP + c) =
                    __floats2half2_rn(fmaxf(acc[mi][ni][2] + bv0, 0.f),
                                      fmaxf(acc[mi][ni][3] + bv1, 0.f));
            }
        __syncthreads();
        const int ped0 = R0 / NP;
        const int pedN = (R0 + 127) / NP - ped0 + 1;   // <= 6
        for (int it = tid; it < pedN * 128; it += 256) {
            int pl = it >> 7, c = it & 127;
            int gp = ped0 + pl;
            int rs = gp * NP - R0, re = rs + NP;
            if (rs < 0) rs = 0;
            if (re > 128) re = 128;
            float v = 0.f;
            for (int rr = rs; rr < re; rr++) v = fmaxf(v, __half2float(Dsm[rr * DP + c]));
            atomicMax((int*)&g_pool[(size_t)gp * BNK + n0 + c], __float_as_int(v));
        }
        __syncthreads();
    }
}

// ---------------- mlp1 via mma.sync fp16: g_dh = relu([hmid|pool] @ W_m1 + b_m1) --------
#define GP_KC 64
#define KP 72
__global__ __launch_bounds__(256) void mlp1_mma(const float* __restrict__ bm1) {
    __shared__ __half As[64 * KP];
    __shared__ __half Bs[128 * KP];
    const int tid = threadIdx.x;
    const int wid = tid >> 5, lane = tid & 31;
    const int gid = lane >> 2, tig = lane & 3;
    const int wm = (wid & 1) * 32, wn = (wid >> 1) * 32;
    const int n0 = blockIdx.x * 128, m0 = blockIdx.y * 64;
    const __half* Bg = g_Wm1t + (size_t)n0 * KTOT;
    const uint32_t sbA = smem_u32(As);
    const uint32_t sbB = smem_u32(Bs);
    const int lrow = tid >> 3;
    const int lcol = (tid & 7) * 8;
    const int q = lane >> 3;
    const int mrow = (q & 1) * 8 + (lane & 7);
    const int mkof = (q >> 1) * 8;

    float acc[2][4][4] = {};

    for (int kc = 0; kc < KTOT; kc += GP_KC) {
#pragma unroll
        for (int p = 0; p < 4; p++) {
            int row = lrow + p * 32;
            cp_async16(sbB + (uint32_t)(row * KP + lcol) * 2,
                       Bg + (size_t)row * KTOT + kc + lcol);
        }
        CP_COMMIT();
#pragma unroll
        for (int p = 0; p < 2; p++) {
            int row = lrow + p * 32;
            int k = kc + lcol;
            const float* src = (k < HDIM) ? (g_hmid + (size_t)(m0 + row) * HDIM + k)
                                          : (g_pool + (size_t)(m0 + row) * BNK + (k - HDIM));
            float4 v0 = ((const float4*)src)[0];
            float4 v1 = ((const float4*)src)[1];
            __half2* da = (__half2*)(As + row * KP + lcol);
            da[0] = __floats2half2_rn(v0.x, v0.y);
            da[1] = __floats2half2_rn(v0.z, v0.w);
            da[2] = __floats2half2_rn(v1.x, v1.y);
            da[3] = __floats2half2_rn(v1.z, v1.w);
        }
        CP_WAIT(0);
        __syncthreads();
#pragma unroll
        for (int kk = 0; kk < GP_KC; kk += 16) {
            uint32_t af[2][4], bf[4][2];
#pragma unroll
            for (int mi = 0; mi < 2; mi++) {
                uint32_t addr = sbA + (uint32_t)((wm + mi * 16 + mrow) * KP + kk + mkof) * 2;
                ldsm_x4(af[mi], addr);
            }
#pragma unroll
            for (int pi = 0; pi < 2; pi++) {
                uint32_t r[4];
                uint32_t addr = sbB + (uint32_t)((wn + pi * 16 + mrow) * KP + kk + mkof) * 2;
                ldsm_x4(r, addr);
                bf[2 * pi][0] = r[0]; bf[2 * pi][1] = r[2];
                bf[2 * pi + 1][0] = r[1]; bf[2 * pi + 1][1] = r[3];
            }
#pragma unroll
            for (int mi = 0; mi < 2; mi++)
#pragma unroll
                for (int ni = 0; ni < 4; ni++)
                    mma_f16(acc[mi][ni], af[mi], bf[ni]);
        }
        __syncthreads();
    }
#pragma unroll
    for (int mi = 0; mi < 2; mi++)
#pragma unroll
        for (int ni = 0; ni < 4; ni++) {
            int r = m0 + wm + mi * 16 + gid;
            int c = n0 + wn + ni * 8 + 2 * tig;
            float bv0 = bm1[c], bv1 = bm1[c + 1];
            g_dh[(size_t)r * MLPD + c]           = fmaxf(acc[mi][ni][0] + bv0, 0.f);
            g_dh[(size_t)r * MLPD + c + 1]       = fmaxf(acc[mi][ni][1] + bv1, 0.f);
            g_dh[(size_t)(r + 8) * MLPD + c]     = fmaxf(acc[mi][ni][2] + bv0, 0.f);
            g_dh[(size_t)(r + 8) * MLPD + c + 1] = fmaxf(acc[mi][ni][3] + bv1, 0.f);
        }
}

// ---------------- decoder MLP layer 2: h = relu(dh @ W_m2 + b_m2) ----------------
__global__ __launch_bounds__(256) void mlp2_kernel(const float* __restrict__ Wm2,
                                                   const float* __restrict__ bm2) {
    const int m0 = blockIdx.x * 32;
    const int tid = threadIdx.x, tx = tid & 15, ty = tid >> 4;
    __shared__ float As[32][KC + 1];
    __shared__ float Bs[KC][128];
    float acc[2][8];
#pragma unroll
    for (int mm = 0; mm < 2; mm++)
#pragma unroll
        for (int nn = 0; nn < 8; nn++) acc[mm][nn] = 0.f;

    for (int kc = 0; kc < MLPD; kc += KC) {
#pragma unroll
        for (int p = 0; p < 2; p++) {
            int idx = tid + p * 256;
            int m = idx >> 4, kk = idx & 15;
            As[m][kk] = g_dh[(size_t)(m0 + m) * MLPD + kc + kk];
        }
#pragma unroll
        for (int p = 0; p < 8; p++) {
            int idx = tid + p * 256;
            int kk = idx >> 7, nn = idx & 127;
            Bs[kk][nn] = Wm2[(size_t)(kc + kk) * HDIM + nn];
        }
        __syncthreads();
#pragma unroll
        for (int kk = 0; kk < KC; kk++) {
            float a[2];
            a[0] = As[ty * 2][kk];
            a[1] = As[ty * 2 + 1][kk];
            float4 b0 = *(const float4*)&Bs[kk][tx * 8];
            float4 b1 = *(const float4*)&Bs[kk][tx * 8 + 4];
#pragma unroll
            for (int mm = 0; mm < 2; mm++) {
                acc[mm][0] += a[mm] * b0.x; acc[mm][1] += a[mm] * b0.y;
                acc[mm][2] += a[mm] * b0.z; acc[mm][3] += a[mm] * b0.w;
                acc[mm][4] += a[mm] * b1.x; acc[mm][5] += a[mm] * b1.y;
                acc[mm][6] += a[mm] * b1.z; acc[mm][7] += a[mm] * b1.w;
            }
        }
        __syncthreads();
    }
#pragma unroll
    for (int mm = 0; mm < 2; mm++)
#pragma unroll
        for (int nn = 0; nn < 8; nn++) {
            int n = tx * 8 + nn;
            g_h[(size_t)(m0 + ty * 2 + mm) * HDIM + n] = fmaxf(acc[mm][nn] + bm2[n], 0.f);
        }
}

__global__ void copy_h_kernel(float* __restrict__ out) {
    int i = blockIdx.x * blockDim.x + threadIdx.x;
    if (i < BATCH * HDIM) out[i] = g_h[i];
}

// ---------------- launch ----------------
extern "C" void kernel_launch(void* const* d_in, const int* in_sizes, int n_in,
                              void* d_out, int out_size) {
    const float* last_pos     = (const float*)d_in[0];
    const float* last_pos_rel = (const float*)d_in[1];
    const float* h0   = (const float*)d_in[2];
    const float* c0   = (const float*)d_in[3];
    /* d_in[4] = seq_start_end (uniform scenes; unused) */
    const float* W_se = (const float*)d_in[5];
    const float* b_se = (const float*)d_in[6];
    const float* W_ih = (const float*)d_in[7];
    const float* b_ih = (const float*)d_in[8];
    const float* W_hh = (const float*)d_in[9];
    const float* b_hh = (const float*)d_in[10];
    const float* W_hp = (const float*)d_in[11];
    const float* b_hp = (const float*)d_in[12];
    const float* W_pse = (const float*)d_in[13];
    const float* b_pse = (const float*)d_in[14];
    const float* W_p1 = (const float*)d_in[15];
    const float* b_p1 = (const float*)d_in[16];
    const float* W_p2 = (const float*)d_in[17];
    const float* b_p2 = (const float*)d_in[18];
    const float* W_m1 = (const float*)d_in[19];
    const float* b_m1 = (const float*)d_in[20];
    const float* W_m2 = (const float*)d_in[21];
    const float* b_m2 = (const float*)d_in[22];
    float* out = (float*)d_out;

    cudaFuncSetAttribute(gemm_pool_mma, cudaFuncAttributeMaxDynamicSharedMemorySize, SMEM_GP);

    setup_kernel<<<96, 256>>>(last_pos, last_pos_rel, h0, c0, W_se, b_se, W_pse, b_pse,
                              W_p1, b_p1, W_p2, W_m1);
    for (int t = 0; t < TSTEPS; t++) {
        lstm_kernel<<<BATCH / 16, 512>>>(W_ih, b_ih, W_hh, b_hh, W_hp, b_hp, W_se, b_se,
                                         W_p1, out + (size_t)t * BATCH * 2);
        layer1_kernel<<<BATCH, 512>>>();
        gemm_pool_mma<<<dim3(8, 18), 256, SMEM_GP>>>(b_p2);
        mlp1_mma<<<dim3(BNK / 128, BATCH / 64), 256>>>(b_m1);
        mlp2_kernel<<<24, 256>>>(W_m2, b_m2);
    }
    copy_h_kernel<<<(BATCH * HDIM + 255) / 256, 256>>>(out + TSTEPS * BATCH * 2);
}

// round 8
// speedup vs baseline: 1.0139x; 1.0139x over previous
#include <cuda_runtime.h>
#include <cuda_fp16.h>
#include <math.h>
#include <stdint.h>

#define BATCH 768
#define NS 32
#define NP 24
#define EDIM 64
#define HDIM 128
#define G4 512      // 4*HDIM
#define P1D 512     // pool hidden
#define BNK 1024
#define MLPD 1024
#define KTOT (HDIM + BNK)   // 1152
#define TSTEPS 12
#define KC 16

// ---------------- scratch (static device memory; no allocations) ----------------
__device__ float g_pos[BATCH * 2];
__device__ float g_decin[BATCH * EDIM];
__device__ float g_h[BATCH * HDIM];
__device__ float g_c[BATCH * HDIM];
__device__ float g_hmid[BATCH * HDIM];
__device__ float g_hterm[BATCH * P1D];
__device__ float g_pool[(size_t)BATCH * BNK];
__device__ float g_dh[(size_t)BATCH * MLPD];
__device__ float g_M2[2 * P1D];
__device__ float g_cb[P1D];
__device__ __half g_Wp2t[(size_t)BNK * P1D];       // W_p2^T fp16
__device__ __half g_Wm1t[(size_t)MLPD * KTOT];     // W_m1^T fp16

__device__ __forceinline__ float sigf(float x) { return 1.f / (1.f + expf(-x)); }

// warp-level fp16 HMMA (generic PTX, sm_80+): m16n8k16, fp32 accum
__device__ __forceinline__ void mma_f16(float* d, const uint32_t* a, const uint32_t* b) {
    asm volatile(
        "mma.sync.aligned.m16n8k16.row.col.f32.f16.f16.f32 "
        "{%0,%1,%2,%3}, {%4,%5,%6,%7}, {%8,%9}, {%0,%1,%2,%3};"
        : "+f"(d[0]), "+f"(d[1]), "+f"(d[2]), "+f"(d[3])
        : "r"(a[0]), "r"(a[1]), "r"(a[2]), "r"(a[3]), "r"(b[0]), "r"(b[1]));
}

__device__ __forceinline__ void ldsm_x4(uint32_t* r, uint32_t saddr) {
    asm volatile("ldmatrix.sync.aligned.m8n8.x4.shared.b16 {%0,%1,%2,%3}, [%4];"
                 : "=r"(r[0]), "=r"(r[1]), "=r"(r[2]), "=r"(r[3]) : "r"(saddr));
}

__device__ __forceinline__ uint32_t smem_u32(const void* p) {
    uint32_t a;
    asm("{ .reg .u64 t; cvta.to.shared.u64 t, %1; cvt.u32.u64 %0, t; }" : "=r"(a) : "l"(p));
    return a;
}
__device__ __forceinline__ void cp_async16(uint32_t saddr, const void* g) {
    asm volatile("cp.async.cg.shared.global [%0], [%1], 16;" :: "r"(saddr), "l"(g));
}
#define CP_COMMIT() asm volatile("cp.async.commit_group;" ::: "memory")
#define CP_WAIT(n)  asm volatile("cp.async.wait_group %0;" :: "n"(n) : "memory")

// ---------------- setup ----------------
__global__ void setup_kernel(const float* __restrict__ last_pos,
                             const float* __restrict__ last_pos_rel,
                             const float* __restrict__ h0, const float* __restrict__ c0,
                             const float* __restrict__ W_se, const float* __restrict__ b_se,
                             const float* __restrict__ W_pse, const float* __restrict__ b_pse,
                             const float* __restrict__ W_p1, const float* __restrict__ b_p1,
                             const float* __restrict__ W_p2, const float* __restrict__ W_m1) {
    int tid = blockIdx.x * blockDim.x + threadIdx.x;
    int nt = gridDim.x * blockDim.x;
    for (int i = tid; i < BATCH * 2; i += nt) g_pos[i] = last_pos[i];
    for (int i = tid; i < BATCH * HDIM; i += nt) { g_h[i] = h0[i]; g_c[i] = c0[i]; }
    for (int i = tid; i < BATCH * EDIM; i += nt) {
        int b = i >> 6, e = i & 63;
        g_decin[i] = b_se[e] + last_pos_rel[b * 2] * W_se[e] + last_pos_rel[b * 2 + 1] * W_se[EDIM + e];
    }
    for (int i = tid; i < 2 * P1D; i += nt) {
        int d = i >> 9, t = i & 511;
        float a = 0.f;
        for (int e = 0; e < EDIM; e++) a += W_pse[d * EDIM + e] * W_p1[e * P1D + t];
        g_M2[i] = a;
    }
    for (int i = tid; i < P1D; i += nt) {
        float a = b_p1[i];
        for (int e = 0; e < EDIM; e++) a += b_pse[e] * W_p1[e * P1D + i];
        g_cb[i] = a;
    }
    for (int i = tid; i < BNK * P1D; i += nt) {
        int n = i / P1D, k = i % P1D;
        g_Wp2t[i] = __float2half_rn(W_p2[(size_t)k * BNK + n]);
    }
    for (int i = tid; i < MLPD * KTOT; i += nt) {
        int n = i / KTOT, k = i % KTOT;
        g_Wm1t[i] = __float2half_rn(W_m1[(size_t)k * MLPD + n]);
    }
}

// ---------------- fused LSTM step + hidden2pos + pos + dec_in + hterm + pool-zero -------
__global__ __launch_bounds__(512) void lstm_kernel(
    const float* __restrict__ W_ih, const float* __restrict__ b_ih,
    const float* __restrict__ W_hh, const float* __restrict__ b_hh,
    const float* __restrict__ W_hp, const float* __restrict__ b_hp,
    const float* __restrict__ W_se, const float* __restrict__ b_se,
    const float* __restrict__ W_p1,
    float* __restrict__ pred_out) {
    __shared__ float s_x[16 * EDIM];
    __shared__ float s_h[16 * HDIM];
    __shared__ float s_g[16 * G4];
    __shared__ float s_rel[32];
    int tid = threadIdx.x;
    int row0 = blockIdx.x * 16;
    // zero this block's pool rows (atomicMax targets)
    {
        float4 z = make_float4(0.f, 0.f, 0.f, 0.f);
        float4* pz = (float4*)(g_pool + (size_t)row0 * BNK);
        for (int i = tid; i < 16 * BNK / 4; i += 512) pz[i] = z;
    }
    for (int i = tid; i < 16 * EDIM; i += 512) s_x[i] = g_decin[row0 * EDIM + i];
    for (int i = tid; i < 16 * HDIM; i += 512) s_h[i] = g_h[row0 * HDIM + i];
    __syncthreads();
    {
        float acc[16];
        float bb = b_ih[tid] + b_hh[tid];
#pragma unroll
        for (int r = 0; r < 16; r++) acc[r] = bb;
        for (int k = 0; k < EDIM; k++) {
            float w = W_ih[k * G4 + tid];
#pragma unroll
            for (int r = 0; r < 16; r++) acc[r] += w * s_x[r * EDIM + k];
        }
        for (int k = 0; k < HDIM; k++) {
            float w = W_hh[k * G4 + tid];
#pragma unroll
            for (int r = 0; r < 16; r++) acc[r] += w * s_h[r * HDIM + k];
        }
#pragma unroll
        for (int r = 0; r < 16; r++) s_g[r * G4 + tid] = acc[r];
    }
    __syncthreads();
    for (int i = tid; i < 16 * HDIM; i += 512) {
        int r = i >> 7, hc = i & 127;
        const float* gr = s_g + r * G4;
        float ig = sigf(gr[hc]);
        float fg = sigf(gr[HDIM + hc]);
        float gg = tanhf(gr[2 * HDIM + hc]);
        float og = sigf(gr[3 * HDIM + hc]);
        float c = fg * g_c[(row0 + r) * HDIM + hc] + ig * gg;
        float hn = og * tanhf(c);
        g_c[(row0 + r) * HDIM + hc] = c;
        g_hmid[(row0 + r) * HDIM + hc] = hn;
        s_h[r * HDIM + hc] = hn;
    }
    __syncthreads();
    if (tid < 32) {
        int r = tid >> 1, d = tid & 1;
        float a = b_hp[d];
        for (int k = 0; k < HDIM; k++) a += s_h[r * HDIM + k] * W_hp[k * 2 + d];
        s_rel[tid] = a;
        pred_out[row0 * 2 + tid] = a;
        g_pos[row0 * 2 + tid] = a + g_pos[row0 * 2 + tid];
    }
    __syncthreads();
    for (int i = tid; i < 16 * EDIM; i += 512) {
        int r = i >> 6, e = i & 63;
        g_decin[(row0 + r) * EDIM + e] =
            b_se[e] + s_rel[r * 2] * W_se[e] + s_rel[r * 2 + 1] * W_se[EDIM + e];
    }
    // ---- fused hterm: hterm[row0+r][tid] = cb[tid] + sum_k h_new[r][k] * W_p1[64+k][tid]
    {
        float acc[16];
        float cb = g_cb[tid];
#pragma unroll
        for (int r = 0; r < 16; r++) acc[r] = cb;
        for (int k = 0; k < HDIM; k++) {
            float w = W_p1[(EDIM + k) * P1D + tid];
#pragma unroll
            for (int r = 0; r < 16; r++) acc[r] += w * s_h[r * HDIM + k];
        }
#pragma unroll
        for (int r = 0; r < 16; r++) g_hterm[(row0 + r) * P1D + tid] = acc[r];
    }
}

// ---------------- fused layer1 + GEMM + pool ----------------
// grid (144): each CTA owns one 128-row m-block (rows = (s,i,j) flattened).
// A (128x512 fp16) computed IN-KERNEL from hterm/pos/M2 into resident smem.
// B (g_Wp2t) streamed as double-buffered 16KB chunks over 8 n-tiles x 8 k-chunks.
#define SMB_A 0
#define SMB_B 131072
#define SMB_D 163840
#define SMEM_GP (163840 + 128 * 136 * 2)   // 198656
#define DP 136

__global__ __launch_bounds__(256) void gemm_pool_mma(const float* __restrict__ bp2) {
    extern __shared__ char smraw[];
    const uint32_t sb = smem_u32(smraw);
    const uint32_t sbA = sb + SMB_A;
    const uint32_t sbB = sb + SMB_B;
    __half* Dsm = (__half*)(smraw + SMB_D);
    // meta overlays the D region (dead before first epilogue)
    float* sdx = (float*)(smraw + SMB_D);
    float* sdy = sdx + 128;
    int* sjr = (int*)(sdy + 128);
    float* sm0 = (float*)(sjr + 128);
    float* sm1 = sm0 + 512;

    const int tid = threadIdx.x;
    const int wid = tid >> 5, lane = tid & 31;
    const int gid = lane >> 2, tig = lane & 3;
    const int wm = (wid & 1) * 64, wn = (wid >> 1) * 32;
    const int R0 = blockIdx.x * 128;
    const int q = lane >> 3;
    const int mrow = (q & 1) * 8 + (lane & 7);
    const int mkof = (q >> 1) * 8;
    const uint32_t swz = (uint32_t)(lane & 7) << 4;

    // ---- per-row meta + M2 staging ----
    if (tid < 128) {
        int gr = R0 + tid;
        int s = gr / 576;
        int rem = gr - s * 576;
        int i = rem / 24;
        int j = rem - i * 24;
        int jped = s * 24 + j, iped = s * 24 + i;
        sjr[tid] = jped;
        sdx[tid] = g_pos[jped * 2] - g_pos[iped * 2];
        sdy[tid] = g_pos[jped * 2 + 1] - g_pos[iped * 2 + 1];
    }
    for (int k = tid; k < P1D; k += 256) { sm0[k] = g_M2[k]; sm1[k] = g_M2[P1D + k]; }
    __syncthreads();

    // ---- A fill: A[r][k] = fp16(relu(hterm[jped][k] + dx*m0[k] + dy*m1[k])) ----
    for (int p = 0; p < 32; p++) {
        int idx = tid + p * 256;          // 0..8191
        int r = idx >> 6, sg = idx & 63;
        int k0 = sg * 8;
        const float4* hp = (const float4*)(g_hterm + (size_t)sjr[r] * P1D + k0);
        float4 h0 = hp[0], h1 = hp[1];
        float dx = sdx[r], dy = sdy[r];
        float4 a0 = *(const float4*)(sm0 + k0), a1 = *(const float4*)(sm0 + k0 + 4);
        float4 c0 = *(const float4*)(sm1 + k0), c1 = *(const float4*)(sm1 + k0 + 4);
        __half2 o[4];
        o[0] = __floats2half2_rn(fmaxf(h0.x + dx * a0.x + dy * c0.x, 0.f),
                                 fmaxf(h0.y + dx * a0.y + dy * c0.y, 0.f));
        o[1] = __floats2half2_rn(fmaxf(h0.z + dx * a0.z + dy * c0.z, 0.f),
                                 fmaxf(h0.w + dx * a0.w + dy * c0.w, 0.f));
        o[2] = __floats2half2_rn(fmaxf(h1.x + dx * a1.x + dy * c1.x, 0.f),
                                 fmaxf(h1.y + dx * a1.y + dy * c1.y, 0.f));
        o[3] = __floats2half2_rn(fmaxf(h1.z + dx * a1.z + dy * c1.z, 0.f),
                                 fmaxf(h1.w + dx * a1.w + dy * c1.w, 0.f));
        uint32_t off = (uint32_t)r * 1024 + (((uint32_t)sg * 16) ^ ((uint32_t)(r & 7) << 4));
        *(uint4*)(smraw + SMB_A + off) = *(uint4*)o;
    }
    __syncthreads();

    // ---- prefetch B chunk 0 (nt=0, ck=0) ----
    {
#pragma unroll
        for (int p = 0; p < 4; p++) {
            int idx = tid + p * 256;
            int row = idx >> 3, seg = idx & 7;
            uint32_t dst = sbB + (uint32_t)row * 128 +
                           (((uint32_t)seg * 16) ^ ((uint32_t)(row & 7) << 4));
            cp_async16(dst, g_Wp2t + (size_t)row * P1D + seg * 8);
        }
        CP_COMMIT();
    }

    int buf = 0;
    for (int nt = 0; nt < 8; nt++) {
        float acc[4][4][4] = {};
        for (int ck = 0; ck < 8; ck++) {
            const int c = nt * 8 + ck + 1;
            if (c < 64) {
                const int nnt = c >> 3, nck = c & 7;
                const __half* src = g_Wp2t + (size_t)nnt * 128 * P1D + nck * 64;
                uint32_t dstb = sbB + (uint32_t)(buf ^ 1) * 16384;
#pragma unroll
                for (int p = 0; p < 4; p++) {
                    int idx = tid + p * 256;
                    int row = idx >> 3, seg = idx & 7;
                    cp_async16(dstb + (uint32_t)row * 128 +
                                   (((uint32_t)seg * 16) ^ ((uint32_t)(row & 7) << 4)),
                               src + (size_t)row * P1D + seg * 8);
                }
                CP_COMMIT();
                CP_WAIT(1);
            } else {
                CP_WAIT(0);
            }
            __syncthreads();
            const uint32_t sBc = sbB + (uint32_t)buf * 16384;
            const uint32_t kbase = (uint32_t)(ck * 64 + mkof) * 2;
#pragma unroll
            for (int kk = 0; kk < 64; kk += 16) {
                const uint32_t kbA = kbase + (uint32_t)kk * 2;   // byte offset in A row
                const uint32_t kbB = (uint32_t)(kk + mkof) * 2;  // byte offset in B row
                uint32_t af[4][4], bf[4][2];
#pragma unroll
                for (int mi = 0; mi < 4; mi++) {
                    uint32_t addr = sbA + (uint32_t)(wm + mi * 16 + mrow) * 1024 + (kbA ^ swz);
                    ldsm_x4(af[mi], addr);
                }
#pragma unroll
                for (int pi = 0; pi < 2; pi++) {
                    uint32_t r[4];
                    uint32_t addr = sBc + (uint32_t)(wn + pi * 16 + mrow) * 128 + (kbB ^ swz);
                    ldsm_x4(r, addr);
                    bf[2 * pi][0] = r[0]; bf[2 * pi][1] = r[2];
                    bf[2 * pi + 1][0] = r[1]; bf[2 * pi + 1][1] = r[3];
                }
#pragma unroll
                for (int mi = 0; mi < 4; mi++)
#pragma unroll
                    for (int ni = 0; ni < 4; ni++)
                        mma_f16(acc[mi][ni], af[mi], bf[ni]);
            }
            __syncthreads();
            buf ^= 1;
        }
        // ---- epilogue for n-tile nt ----
        const int n0 = nt * 128;
#pragma unroll
        for (int mi = 0; mi < 4; mi++)
#pragma unroll
            for (int ni = 0; ni < 4; ni++) {
                int r = wm + mi * 16 + gid;
                int col = wn + ni * 8 + 2 * tig;
                float bv0 = bp2[n0 + col], bv1 = bp2[n0 + col + 1];
                *(__half2*)(Dsm + r * DP + col) =
                    __floats2half2_rn(fmaxf(acc[mi][ni][0] + bv0, 0.f),
                                      fmaxf(acc[mi][ni][1] + bv1, 0.f));
                *(__half2*)(Dsm + (r + 8) * DP + col) =
                    __floats2half2_rn(fmaxf(acc[mi][ni][2] + bv0, 0.f),
                                      fmaxf(acc[mi][ni][3] + bv1, 0.f));
            }
        __syncthreads();
        const int ped0 = R0 / NP;
        const int pedN = (R0 + 127) / NP - ped0 + 1;   // <= 6
        for (int it = tid; it < pedN * 128; it += 256) {
            int pl = it >> 7, col = it & 127;
            int gp = ped0 + pl;
            int rs = gp * NP - R0, re = rs + NP;
            if (rs < 0) rs = 0;
            if (re > 128) re = 128;
            float v = 0.f;
            for (int rr = rs; rr < re; rr++) v = fmaxf(v, __half2float(Dsm[rr * DP + col]));
            atomicMax((int*)&g_pool[(size_t)gp * BNK + n0 + col], __float_as_int(v));
        }
        __syncthreads();
    }
}

// ---------------- mlp1 via mma.sync fp16: g_dh = relu([hmid|pool] @ W_m1 + b_m1) --------
#define GP_KC 64
#define KP 72
__global__ __launch_bounds__(256) void mlp1_mma(const float* __restrict__ bm1) {
    __shared__ __half As[64 * KP];
    __shared__ __half Bs[128 * KP];
    const int tid = threadIdx.x;
    const int wid = tid >> 5, lane = tid & 31;
    const int gid = lane >> 2, tig = lane & 3;
    const int wm = (wid & 1) * 32, wn = (wid >> 1) * 32;
    const int n0 = blockIdx.x * 128, m0 = blockIdx.y * 64;
    const __half* Bg = g_Wm1t + (size_t)n0 * KTOT;
    const uint32_t sbA = smem_u32(As);
    const uint32_t sbB = smem_u32(Bs);
    const int lrow = tid >> 3;
    const int lcol = (tid & 7) * 8;
    const int q = lane >> 3;
    const int mrow = (q & 1) * 8 + (lane & 7);
    const int mkof = (q >> 1) * 8;

    float acc[2][4][4] = {};

    for (int kc = 0; kc < KTOT; kc += GP_KC) {
#pragma unroll
        for (int p = 0; p < 4; p++) {
            int row = lrow + p * 32;
            cp_async16(sbB + (uint32_t)(row * KP + lcol) * 2,
                       Bg + (size_t)row * KTOT + kc + lcol);
        }
        CP_COMMIT();
#pragma unroll
        for (int p = 0; p < 2; p++) {
            int row = lrow + p * 32;
            int k = kc + lcol;
            const float* src = (k < HDIM) ? (g_hmid + (size_t)(m0 + row) * HDIM + k)
                                          : (g_pool + (size_t)(m0 + row) * BNK + (k - HDIM));
            float4 v0 = ((const float4*)src)[0];
            float4 v1 = ((const float4*)src)[1];
            __half2* da = (__half2*)(As + row * KP + lcol);
            da[0] = __floats2half2_rn(v0.x, v0.y);
            da[1] = __floats2half2_rn(v0.z, v0.w);
            da[2] = __floats2half2_rn(v1.x, v1.y);
            da[3] = __floats2half2_rn(v1.z, v1.w);
        }
        CP_WAIT(0);
        __syncthreads();
#pragma unroll
        for (int kk = 0; kk < GP_KC; kk += 16) {
            uint32_t af[2][4], bf[4][2];
#pragma unroll
            for (int mi = 0; mi < 2; mi++) {
                uint32_t addr = sbA + (uint32_t)((wm + mi * 16 + mrow) * KP + kk + mkof) * 2;
                ldsm_x4(af[mi], addr);
            }
#pragma unroll
            for (int pi = 0; pi < 2; pi++) {
                uint32_t r[4];
                uint32_t addr = sbB + (uint32_t)((wn + pi * 16 + mrow) * KP + kk + mkof) * 2;
                ldsm_x4(r, addr);
                bf[2 * pi][0] = r[0]; bf[2 * pi][1] = r[2];
                bf[2 * pi + 1][0] = r[1]; bf[2 * pi + 1][1] = r[3];
            }
#pragma unroll
            for (int mi = 0; mi < 2; mi++)
#pragma unroll
                for (int ni = 0; ni < 4; ni++)
                    mma_f16(acc[mi][ni], af[mi], bf[ni]);
        }
        __syncthreads();
    }
#pragma unroll
    for (int mi = 0; mi < 2; mi++)
#pragma unroll
        for (int ni = 0; ni < 4; ni++) {
            int r = m0 + wm + mi * 16 + gid;
            int c = n0 + wn + ni * 8 + 2 * tig;
            float bv0 = bm1[c], bv1 = bm1[c + 1];
            g_dh[(size_t)r * MLPD + c]           = fmaxf(acc[mi][ni][0] + bv0, 0.f);
            g_dh[(size_t)r * MLPD + c + 1]       = fmaxf(acc[mi][ni][1] + bv1, 0.f);
            g_dh[(size_t)(r + 8) * MLPD + c]     = fmaxf(acc[mi][ni][2] + bv0, 0.f);
            g_dh[(size_t)(r + 8) * MLPD + c + 1] = fmaxf(acc[mi][ni][3] + bv1, 0.f);
        }
}

// ---------------- decoder MLP layer 2: h = relu(dh @ W_m2 + b_m2) ----------------
__global__ __launch_bounds__(256) void mlp2_kernel(const float* __restrict__ Wm2,
                                                   const float* __restrict__ bm2) {
    const int m0 = blockIdx.x * 32;
    const int tid = threadIdx.x, tx = tid & 15, ty = tid >> 4;
    __shared__ float As[32][KC + 1];
    __shared__ float Bs[KC][128];
    float acc[2][8];
#pragma unroll
    for (int mm = 0; mm < 2; mm++)
#pragma unroll
        for (int nn = 0; nn < 8; nn++) acc[mm][nn] = 0.f;

    for (int kc = 0; kc < MLPD; kc += KC) {
#pragma unroll
        for (int p = 0; p < 2; p++) {
            int idx = tid + p * 256;
            int m = idx >> 4, kk = idx & 15;
            As[m][kk] = g_dh[(size_t)(m0 + m) * MLPD + kc + kk];
        }
#pragma unroll
        for (int p = 0; p < 8; p++) {
            int idx = tid + p * 256;
            int kk = idx >> 7, nn = idx & 127;
            Bs[kk][nn] = Wm2[(size_t)(kc + kk) * HDIM + nn];
        }
        __syncthreads();
#pragma unroll
        for (int kk = 0; kk < KC; kk++) {
            float a[2];
            a[0] = As[ty * 2][kk];
            a[1] = As[ty * 2 + 1][kk];
            float4 b0 = *(const float4*)&Bs[kk][tx * 8];
            float4 b1 = *(const float4*)&Bs[kk][tx * 8 + 4];
#pragma unroll
            for (int mm = 0; mm < 2; mm++) {
                acc[mm][0] += a[mm] * b0.x; acc[mm][1] += a[mm] * b0.y;
                acc[mm][2] += a[mm] * b0.z; acc[mm][3] += a[mm] * b0.w;
                acc[mm][4] += a[mm] * b1.x; acc[mm][5] += a[mm] * b1.y;
                acc[mm][6] += a[mm] * b1.z; acc[mm][7] += a[mm] * b1.w;
            }
        }
        __syncthreads();
    }
#pragma unroll
    for (int mm = 0; mm < 2; mm++)
#pragma unroll
        for (int nn = 0; nn < 8; nn++) {
            int n = tx * 8 + nn;
            g_h[(size_t)(m0 + ty * 2 + mm) * HDIM + n] = fmaxf(acc[mm][nn] + bm2[n], 0.f);
        }
}

__global__ void copy_h_kernel(float* __restrict__ out) {
    int i = blockIdx.x * blockDim.x + threadIdx.x;
    if (i < BATCH * HDIM) out[i] = g_h[i];
}

// ---------------- launch ----------------
extern "C" void kernel_launch(void* const* d_in, const int* in_sizes, int n_in,
                              void* d_out, int out_size) {
    const float* last_pos     = (const float*)d_in[0];
    const float* last_pos_rel = (const float*)d_in[1];
    const float* h0   = (const float*)d_in[2];
    const float* c0   = (const float*)d_in[3];
    /* d_in[4] = seq_start_end (uniform scenes; unused) */
    const float* W_se = (const float*)d_in[5];
    const float* b_se = (const float*)d_in[6];
    const float* W_ih = (const float*)d_in[7];
    const float* b_ih = (const float*)d_in[8];
    const float* W_hh = (const float*)d_in[9];
    const float* b_hh = (const float*)d_in[10];
    const float* W_hp = (const float*)d_in[11];
    const float* b_hp = (const float*)d_in[12];
    const float* W_pse = (const float*)d_in[13];
    const float* b_pse = (const float*)d_in[14];
    const float* W_p1 = (const float*)d_in[15];
    const float* b_p1 = (const float*)d_in[16];
    const float* W_p2 = (const float*)d_in[17];
    const float* b_p2 = (const float*)d_in[18];
    const float* W_m1 = (const float*)d_in[19];
    const float* b_m1 = (const float*)d_in[20];
    const float* W_m2 = (const float*)d_in[21];
    const float* b_m2 = (const float*)d_in[22];
    float* out = (float*)d_out;

    cudaFuncSetAttribute(gemm_pool_mma, cudaFuncAttributeMaxDynamicSharedMemorySize, SMEM_GP);

    setup_kernel<<<96, 256>>>(last_pos, last_pos_rel, h0, c0, W_se, b_se, W_pse, b_pse,
                              W_p1, b_p1, W_p2, W_m1);
    for (int t = 0; t < TSTEPS; t++) {
        lstm_kernel<<<BATCH / 16, 512>>>(W_ih, b_ih, W_hh, b_hh, W_hp, b_hp, W_se, b_se,
                                         W_p1, out + (size_t)t * BATCH * 2);
        gemm_pool_mma<<<(BATCH * NP) / 128, 256, SMEM_GP>>>(b_p2);
        mlp1_mma<<<dim3(BNK / 128, BATCH / 64), 256>>>(b_m1);
        mlp2_kernel<<<24, 256>>>(W_m2, b_m2);
    }
    copy_h_kernel<<<(BATCH * HDIM + 255) / 256, 256>>>(out + TSTEPS * BATCH * 2);
}

// round 9
// speedup vs baseline: 1.1432x; 1.1275x over previous
#include <cuda_runtime.h>
#include <cuda_fp16.h>
#include <math.h>
#include <stdint.h>

#define BATCH 768
#define NS 32
#define NP 24
#define EDIM 64
#define HDIM 128
#define G4 512      // 4*HDIM
#define P1D 512     // pool hidden
#define BNK 1024
#define MLPD 1024
#define KTOT (HDIM + BNK)   // 1152
#define TSTEPS 12
#define NCTA 144

// ---------------- scratch (static device memory; no allocations) ----------------
__device__ float g_pos[BATCH * 2];
__device__ float g_decin[BATCH * EDIM];
__device__ float g_h[BATCH * HDIM];
__device__ float g_c[BATCH * HDIM];
__device__ float g_hmid[BATCH * HDIM];
__device__ float g_hterm[BATCH * P1D];
__device__ float g_pool[(size_t)BATCH * BNK];
__device__ float g_dh[(size_t)BATCH * MLPD];
__device__ float g_M2[2 * P1D];
__device__ float g_cb[P1D];
__device__ __half g_Wp2t[(size_t)BNK * P1D];       // W_p2^T fp16
__device__ __half g_Wm1t[(size_t)MLPD * KTOT];     // W_m1^T fp16
__device__ unsigned g_bar_count;
__device__ unsigned g_bar_sense;

__device__ __forceinline__ float sigf(float x) { return 1.f / (1.f + expf(-x)); }

// warp-level fp16 HMMA (generic PTX, sm_80+): m16n8k16, fp32 accum
__device__ __forceinline__ void mma_f16(float* d, const uint32_t* a, const uint32_t* b) {
    asm volatile(
        "mma.sync.aligned.m16n8k16.row.col.f32.f16.f16.f32 "
        "{%0,%1,%2,%3}, {%4,%5,%6,%7}, {%8,%9}, {%0,%1,%2,%3};"
        : "+f"(d[0]), "+f"(d[1]), "+f"(d[2]), "+f"(d[3])
        : "r"(a[0]), "r"(a[1]), "r"(a[2]), "r"(a[3]), "r"(b[0]), "r"(b[1]));
}

__device__ __forceinline__ void ldsm_x4(uint32_t* r, uint32_t saddr) {
    asm volatile("ldmatrix.sync.aligned.m8n8.x4.shared.b16 {%0,%1,%2,%3}, [%4];"
                 : "=r"(r[0]), "=r"(r[1]), "=r"(r[2]), "=r"(r[3]) : "r"(saddr));
}

__device__ __forceinline__ uint32_t smem_u32(const void* p) {
    uint32_t a;
    asm("{ .reg .u64 t; cvta.to.shared.u64 t, %1; cvt.u32.u64 %0, t; }" : "=r"(a) : "l"(p));
    return a;
}
__device__ __forceinline__ void cp_async16(uint32_t saddr, const void* g) {
    asm volatile("cp.async.cg.shared.global [%0], [%1], 16;" :: "r"(saddr), "l"(g));
}
#define CP_COMMIT() asm volatile("cp.async.commit_group;" ::: "memory")
#define CP_WAIT(n)  asm volatile("cp.async.wait_group %0;" :: "n"(n) : "memory")

// ---- software grid barrier (all NCTA CTAs resident by construction) ----
__device__ __forceinline__ void grid_bar(unsigned target) {
    __syncthreads();
    if (threadIdx.x == 0) {
        __threadfence();
        unsigned old = atomicAdd(&g_bar_count, 1);
        if (old == NCTA - 1) {
            g_bar_count = 0;
            __threadfence();
            atomicAdd(&g_bar_sense, 1);
        } else {
            while ((int)(*(volatile unsigned*)&g_bar_sense - target) < 0)
                __nanosleep(64);
        }
        __threadfence();
    }
    __syncthreads();
}

// ---------------- setup ----------------
__global__ void setup_kernel(const float* __restrict__ last_pos,
                             const float* __restrict__ last_pos_rel,
                             const float* __restrict__ h0, const float* __restrict__ c0,
                             const float* __restrict__ W_se, const float* __restrict__ b_se,
                             const float* __restrict__ W_pse, const float* __restrict__ b_pse,
                             const float* __restrict__ W_p1, const float* __restrict__ b_p1,
                             const float* __restrict__ W_p2, const float* __restrict__ W_m1) {
    int tid = blockIdx.x * blockDim.x + threadIdx.x;
    int nt = gridDim.x * blockDim.x;
    for (int i = tid; i < BATCH * 2; i += nt) g_pos[i] = last_pos[i];
    for (int i = tid; i < BATCH * HDIM; i += nt) { g_h[i] = h0[i]; g_c[i] = c0[i]; }
    for (int i = tid; i < BATCH * EDIM; i += nt) {
        int b = i >> 6, e = i & 63;
        g_decin[i] = b_se[e] + last_pos_rel[b * 2] * W_se[e] + last_pos_rel[b * 2 + 1] * W_se[EDIM + e];
    }
    for (int i = tid; i < 2 * P1D; i += nt) {
        int d = i >> 9, t = i & 511;
        float a = 0.f;
        for (int e = 0; e < EDIM; e++) a += W_pse[d * EDIM + e] * W_p1[e * P1D + t];
        g_M2[i] = a;
    }
    for (int i = tid; i < P1D; i += nt) {
        float a = b_p1[i];
        for (int e = 0; e < EDIM; e++) a += b_pse[e] * W_p1[e * P1D + i];
        g_cb[i] = a;
    }
    for (int i = tid; i < BNK * P1D; i += nt) {
        int n = i / P1D, k = i % P1D;
        g_Wp2t[i] = __float2half_rn(W_p2[(size_t)k * BNK + n]);
    }
    for (int i = tid; i < MLPD * KTOT; i += nt) {
        int n = i / KTOT, k = i % KTOT;
        g_Wm1t[i] = __float2half_rn(W_m1[(size_t)k * MLPD + n]);
    }
}

// ---------------- persistent all-steps kernel ----------------
#define SMB_A 0
#define SMB_B 131072
#define SMB_D 163840
#define SMEM_GP (163840 + 128 * 136 * 2)   // 198656
#define DP 136
#define GP_KC 64
#define KP 72
#define KC 16

__global__ __launch_bounds__(256) void decoder_persistent(
    const float* __restrict__ W_ih, const float* __restrict__ b_ih,
    const float* __restrict__ W_hh, const float* __restrict__ b_hh,
    const float* __restrict__ W_hp, const float* __restrict__ b_hp,
    const float* __restrict__ W_se, const float* __restrict__ b_se,
    const float* __restrict__ W_p1,
    const float* __restrict__ bp2, const float* __restrict__ bm1,
    const float* __restrict__ Wm2, const float* __restrict__ bm2,
    float* __restrict__ out) {
    extern __shared__ char smraw[];
    const int tid = threadIdx.x;
    const int bx = blockIdx.x;
    const int wid = tid >> 5, lane = tid & 31;
    const int gid = lane >> 2, tig = lane & 3;
    const int q = lane >> 3;
    const int mrow = (q & 1) * 8 + (lane & 7);
    const int mkof = (q >> 1) * 8;
    const uint32_t swz = (uint32_t)(lane & 7) << 4;
    const uint32_t sb = smem_u32(smraw);

    unsigned base = *(volatile unsigned*)&g_bar_sense;
    unsigned bc = 0;

    for (int t = 0; t < TSTEPS; t++) {
        // ================= phase A: LSTM + hidden2pos + pos + dec_in + hterm ==========
        if (bx < 96) {
            const int row0 = bx * 8;
            float* s_x = (float*)smraw;             // 8*64
            float* s_h = s_x + 8 * EDIM;            // 8*128
            float* s_g = s_h + 8 * HDIM;            // 8*512
            float* s_rel = s_g + 8 * G4;            // 16
            // zero pool rows (atomicMax targets)
            {
                float4 z = make_float4(0.f, 0.f, 0.f, 0.f);
                float4* pz = (float4*)(g_pool + (size_t)row0 * BNK);
                for (int i = tid; i < 8 * BNK / 4; i += 256) pz[i] = z;
            }
            for (int i = tid; i < 8 * EDIM; i += 256) s_x[i] = g_decin[row0 * EDIM + i];
            for (int i = tid; i < 8 * HDIM; i += 256) s_h[i] = g_h[row0 * HDIM + i];
            __syncthreads();
            {
                float a0[8], a1[8];
                float bb0 = b_ih[tid] + b_hh[tid];
                float bb1 = b_ih[tid + 256] + b_hh[tid + 256];
#pragma unroll
                for (int r = 0; r < 8; r++) { a0[r] = bb0; a1[r] = bb1; }
                for (int k = 0; k < EDIM; k++) {
                    float w0 = W_ih[k * G4 + tid], w1 = W_ih[k * G4 + tid + 256];
#pragma unroll
                    for (int r = 0; r < 8; r++) {
                        float xa = s_x[r * EDIM + k];
                        a0[r] += w0 * xa; a1[r] += w1 * xa;
                    }
                }
                for (int k = 0; k < HDIM; k++) {
                    float w0 = W_hh[k * G4 + tid], w1 = W_hh[k * G4 + tid + 256];
#pragma unroll
                    for (int r = 0; r < 8; r++) {
                        float ha = s_h[r * HDIM + k];
                        a0[r] += w0 * ha; a1[r] += w1 * ha;
                    }
                }
#pragma unroll
                for (int r = 0; r < 8; r++) {
                    s_g[r * G4 + tid] = a0[r];
                    s_g[r * G4 + tid + 256] = a1[r];
                }
            }
            __syncthreads();
            for (int i = tid; i < 8 * HDIM; i += 256) {
                int r = i >> 7, hc = i & 127;
                const float* gr = s_g + r * G4;
                float ig = sigf(gr[hc]);
                float fg = sigf(gr[HDIM + hc]);
                float gg = tanhf(gr[2 * HDIM + hc]);
                float og = sigf(gr[3 * HDIM + hc]);
                float c = fg * g_c[(row0 + r) * HDIM + hc] + ig * gg;
                float hn = og * tanhf(c);
                g_c[(row0 + r) * HDIM + hc] = c;
                g_hmid[(row0 + r) * HDIM + hc] = hn;
                s_h[r * HDIM + hc] = hn;
            }
            __syncthreads();
            if (tid < 16) {
                int r = tid >> 1, d = tid & 1;
                float a = b_hp[d];
                for (int k = 0; k < HDIM; k++) a += s_h[r * HDIM + k] * W_hp[k * 2 + d];
                s_rel[tid] = a;
                out[(size_t)t * BATCH * 2 + row0 * 2 + tid] = a;
                g_pos[row0 * 2 + tid] = a + g_pos[row0 * 2 + tid];
            }
            __syncthreads();
            for (int i = tid; i < 8 * EDIM; i += 256) {
                int r = i >> 6, e = i & 63;
                g_decin[(row0 + r) * EDIM + e] =
                    b_se[e] + s_rel[r * 2] * W_se[e] + s_rel[r * 2 + 1] * W_se[EDIM + e];
            }
            {
                float a0[8], a1[8];
                float cb0 = g_cb[tid], cb1 = g_cb[tid + 256];
#pragma unroll
                for (int r = 0; r < 8; r++) { a0[r] = cb0; a1[r] = cb1; }
                for (int k = 0; k < HDIM; k++) {
                    float w0 = W_p1[(EDIM + k) * P1D + tid];
                    float w1 = W_p1[(EDIM + k) * P1D + tid + 256];
#pragma unroll
                    for (int r = 0; r < 8; r++) {
                        float ha = s_h[r * HDIM + k];
                        a0[r] += w0 * ha; a1[r] += w1 * ha;
                    }
                }
#pragma unroll
                for (int r = 0; r < 8; r++) {
                    g_hterm[(row0 + r) * P1D + tid] = a0[r];
                    g_hterm[(row0 + r) * P1D + tid + 256] = a1[r];
                }
            }
        }
        grid_bar(base + ++bc);

        // ================= phase B: fused layer1 + GEMM + pool ========================
        {
            const uint32_t sbA = sb + SMB_A;
            const uint32_t sbB = sb + SMB_B;
            __half* Dsm = (__half*)(smraw + SMB_D);
            float* sdx = (float*)(smraw + SMB_D);
            float* sdy = sdx + 128;
            int* sjr = (int*)(sdy + 128);
            float* sm0 = (float*)(sjr + 128);
            float* sm1 = sm0 + 512;
            const int wm = (wid & 1) * 64, wn = (wid >> 1) * 32;
            const int R0 = bx * 128;

            if (tid < 128) {
                int gr = R0 + tid;
                int s = gr / 576;
                int rem = gr - s * 576;
                int i = rem / 24;
                int j = rem - i * 24;
                int jped = s * 24 + j, iped = s * 24 + i;
                sjr[tid] = jped;
                sdx[tid] = g_pos[jped * 2] - g_pos[iped * 2];
                sdy[tid] = g_pos[jped * 2 + 1] - g_pos[iped * 2 + 1];
            }
            for (int k = tid; k < P1D; k += 256) { sm0[k] = g_M2[k]; sm1[k] = g_M2[P1D + k]; }
            __syncthreads();

            for (int p = 0; p < 32; p++) {
                int idx = tid + p * 256;
                int r = idx >> 6, sg = idx & 63;
                int k0 = sg * 8;
                const float4* hp = (const float4*)(g_hterm + (size_t)sjr[r] * P1D + k0);
                float4 h0 = hp[0], h1 = hp[1];
                float dx = sdx[r], dy = sdy[r];
                float4 a0 = *(const float4*)(sm0 + k0), a1 = *(const float4*)(sm0 + k0 + 4);
                float4 c0 = *(const float4*)(sm1 + k0), c1 = *(const float4*)(sm1 + k0 + 4);
                __half2 o[4];
                o[0] = __floats2half2_rn(fmaxf(h0.x + dx * a0.x + dy * c0.x, 0.f),
                                         fmaxf(h0.y + dx * a0.y + dy * c0.y, 0.f));
                o[1] = __floats2half2_rn(fmaxf(h0.z + dx * a0.z + dy * c0.z, 0.f),
                                         fmaxf(h0.w + dx * a0.w + dy * c0.w, 0.f));
                o[2] = __floats2half2_rn(fmaxf(h1.x + dx * a1.x + dy * c1.x, 0.f),
                                         fmaxf(h1.y + dx * a1.y + dy * c1.y, 0.f));
                o[3] = __floats2half2_rn(fmaxf(h1.z + dx * a1.z + dy * c1.z, 0.f),
                                         fmaxf(h1.w + dx * a1.w + dy * c1.w, 0.f));
                uint32_t off = (uint32_t)r * 1024 + (((uint32_t)sg * 16) ^ ((uint32_t)(r & 7) << 4));
                *(uint4*)(smraw + SMB_A + off) = *(uint4*)o;
            }
            __syncthreads();

#pragma unroll
            for (int p = 0; p < 4; p++) {
                int idx = tid + p * 256;
                int row = idx >> 3, seg = idx & 7;
                uint32_t dst = sbB + (uint32_t)row * 128 +
                               (((uint32_t)seg * 16) ^ ((uint32_t)(row & 7) << 4));
                cp_async16(dst, g_Wp2t + (size_t)row * P1D + seg * 8);
            }
            CP_COMMIT();

            int buf = 0;
            for (int nt = 0; nt < 8; nt++) {
                float acc[4][4][4] = {};
                for (int ck = 0; ck < 8; ck++) {
                    const int c = nt * 8 + ck + 1;
                    if (c < 64) {
                        const int nnt = c >> 3, nck = c & 7;
                        const __half* src = g_Wp2t + (size_t)nnt * 128 * P1D + nck * 64;
                        uint32_t dstb = sbB + (uint32_t)(buf ^ 1) * 16384;
#pragma unroll
                        for (int p = 0; p < 4; p++) {
                            int idx = tid + p * 256;
                            int row = idx >> 3, seg = idx & 7;
                            cp_async16(dstb + (uint32_t)row * 128 +
                                           (((uint32_t)seg * 16) ^ ((uint32_t)(row & 7) << 4)),
                                       src + (size_t)row * P1D + seg * 8);
                        }
                        CP_COMMIT();
                        CP_WAIT(1);
                    } else {
                        CP_WAIT(0);
                    }
                    __syncthreads();
                    const uint32_t sBc = sbB + (uint32_t)buf * 16384;
                    const uint32_t kbase = (uint32_t)(ck * 64 + mkof) * 2;
#pragma unroll
                    for (int kk = 0; kk < 64; kk += 16) {
                        const uint32_t kbA = kbase + (uint32_t)kk * 2;
                        const uint32_t kbB = (uint32_t)(kk + mkof) * 2;
                        uint32_t af[4][4], bf[4][2];
#pragma unroll
                        for (int mi = 0; mi < 4; mi++) {
                            uint32_t addr = sbA + (uint32_t)(wm + mi * 16 + mrow) * 1024 + (kbA ^ swz);
                            ldsm_x4(af[mi], addr);
                        }
#pragma unroll
                        for (int pi = 0; pi < 2; pi++) {
                            uint32_t r[4];
                            uint32_t addr = sBc + (uint32_t)(wn + pi * 16 + mrow) * 128 + (kbB ^ swz);
                            ldsm_x4(r, addr);
                            bf[2 * pi][0] = r[0]; bf[2 * pi][1] = r[2];
                            bf[2 * pi + 1][0] = r[1]; bf[2 * pi + 1][1] = r[3];
                        }
#pragma unroll
                        for (int mi = 0; mi < 4; mi++)
#pragma unroll
                            for (int ni = 0; ni < 4; ni++)
                                mma_f16(acc[mi][ni], af[mi], bf[ni]);
                    }
                    __syncthreads();
                    buf ^= 1;
                }
                const int n0 = nt * 128;
#pragma unroll
                for (int mi = 0; mi < 4; mi++)
#pragma unroll
                    for (int ni = 0; ni < 4; ni++) {
                        int r = wm + mi * 16 + gid;
                        int col = wn + ni * 8 + 2 * tig;
                        float bv0 = bp2[n0 + col], bv1 = bp2[n0 + col + 1];
                        *(__half2*)(Dsm + r * DP + col) =
                            __floats2half2_rn(fmaxf(acc[mi][ni][0] + bv0, 0.f),
                                              fmaxf(acc[mi][ni][1] + bv1, 0.f));
                        *(__half2*)(Dsm + (r + 8) * DP + col) =
                            __floats2half2_rn(fmaxf(acc[mi][ni][2] + bv0, 0.f),
                                              fmaxf(acc[mi][ni][3] + bv1, 0.f));
                    }
                __syncthreads();
                const int ped0 = R0 / NP;
                const int pedN = (R0 + 127) / NP - ped0 + 1;
                for (int it = tid; it < pedN * 128; it += 256) {
                    int pl = it >> 7, col = it & 127;
                    int gp = ped0 + pl;
                    int rs = gp * NP - R0, re = rs + NP;
                    if (rs < 0) rs = 0;
                    if (re > 128) re = 128;
                    float v = 0.f;
                    for (int rr = rs; rr < re; rr++) v = fmaxf(v, __half2float(Dsm[rr * DP + col]));
                    atomicMax((int*)&g_pool[(size_t)gp * BNK + n0 + col], __float_as_int(v));
                }
                __syncthreads();
            }
        }
        grid_bar(base + ++bc);

        // ================= phase C: mlp1 (fp16 mma) ===================================
        if (bx < 96) {
            __half* As = (__half*)smraw;               // 64*KP
            __half* Bs = As + 64 * KP;                 // 128*KP
            const uint32_t sbA = smem_u32(As);
            const uint32_t sbB = smem_u32(Bs);
            const int wm = (wid & 1) * 32, wn = (wid >> 1) * 32;
            const int n0 = (bx & 7) * 128, m0 = (bx >> 3) * 64;
            const __half* Bg = g_Wm1t + (size_t)n0 * KTOT;
            const int lrow = tid >> 3;
            const int lcol = (tid & 7) * 8;

            float acc[2][4][4] = {};
            for (int kc = 0; kc < KTOT; kc += GP_KC) {
#pragma unroll
                for (int p = 0; p < 4; p++) {
                    int row = lrow + p * 32;
                    cp_async16(sbB + (uint32_t)(row * KP + lcol) * 2,
                               Bg + (size_t)row * KTOT + kc + lcol);
                }
                CP_COMMIT();
#pragma unroll
                for (int p = 0; p < 2; p++) {
                    int row = lrow + p * 32;
                    int k = kc + lcol;
                    const float* src = (k < HDIM) ? (g_hmid + (size_t)(m0 + row) * HDIM + k)
                                                  : (g_pool + (size_t)(m0 + row) * BNK + (k - HDIM));
                    float4 v0 = ((const float4*)src)[0];
                    float4 v1 = ((const float4*)src)[1];
                    __half2* da = (__half2*)(As + row * KP + lcol);
                    da[0] = __floats2half2_rn(v0.x, v0.y);
                    da[1] = __floats2half2_rn(v0.z, v0.w);
                    da[2] = __floats2half2_rn(v1.x, v1.y);
                    da[3] = __floats2half2_rn(v1.z, v1.w);
                }
                CP_WAIT(0);
                __syncthreads();
#pragma unroll
                for (int kk = 0; kk < GP_KC; kk += 16) {
                    uint32_t af[2][4], bf[4][2];
#pragma unroll
                    for (int mi = 0; mi < 2; mi++) {
                        uint32_t addr = sbA + (uint32_t)((wm + mi * 16 + mrow) * KP + kk + mkof) * 2;
                        ldsm_x4(af[mi], addr);
                    }
#pragma unroll
                    for (int pi = 0; pi < 2; pi++) {
                        uint32_t r[4];
                        uint32_t addr = sbB + (uint32_t)((wn + pi * 16 + mrow) * KP + kk + mkof) * 2;
                        ldsm_x4(r, addr);
                        bf[2 * pi][0] = r[0]; bf[2 * pi][1] = r[2];
                        bf[2 * pi + 1][0] = r[1]; bf[2 * pi + 1][1] = r[3];
                    }
#pragma unroll
                    for (int mi = 0; mi < 2; mi++)
#pragma unroll
                        for (int ni = 0; ni < 4; ni++)
                            mma_f16(acc[mi][ni], af[mi], bf[ni]);
                }
                __syncthreads();
            }
#pragma unroll
            for (int mi = 0; mi < 2; mi++)
#pragma unroll
                for (int ni = 0; ni < 4; ni++) {
                    int r = m0 + wm + mi * 16 + gid;
                    int c = n0 + wn + ni * 8 + 2 * tig;
                    float bv0 = bm1[c], bv1 = bm1[c + 1];
                    g_dh[(size_t)r * MLPD + c]           = fmaxf(acc[mi][ni][0] + bv0, 0.f);
                    g_dh[(size_t)r * MLPD + c + 1]       = fmaxf(acc[mi][ni][1] + bv1, 0.f);
                    g_dh[(size_t)(r + 8) * MLPD + c]     = fmaxf(acc[mi][ni][2] + bv0, 0.f);
                    g_dh[(size_t)(r + 8) * MLPD + c + 1] = fmaxf(acc[mi][ni][3] + bv1, 0.f);
                }
        }
        grid_bar(base + ++bc);

        // ================= phase D: mlp2 ==============================================
        if (bx < 24) {
            const int m0 = bx * 32;
            const int tx = tid & 15, ty = tid >> 4;
            float* As = (float*)smraw;                  // [32][KC+1]
            float* Bs = As + 32 * (KC + 1);             // [KC][128]
            float acc[2][8];
#pragma unroll
            for (int mm = 0; mm < 2; mm++)
#pragma unroll
                for (int nn = 0; nn < 8; nn++) acc[mm][nn] = 0.f;

            for (int kc = 0; kc < MLPD; kc += KC) {
#pragma unroll
                for (int p = 0; p < 2; p++) {
                    int idx = tid + p * 256;
                    int m = idx >> 4, kk = idx & 15;
                    As[m * (KC + 1) + kk] = g_dh[(size_t)(m0 + m) * MLPD + kc + kk];
                }
#pragma unroll
                for (int p = 0; p < 8; p++) {
                    int idx = tid + p * 256;
                    int kk = idx >> 7, nn = idx & 127;
                    Bs[kk * 128 + nn] = Wm2[(size_t)(kc + kk) * HDIM + nn];
                }
                __syncthreads();
#pragma unroll
                for (int kk = 0; kk < KC; kk++) {
                    float a[2];
                    a[0] = As[(ty * 2) * (KC + 1) + kk];
                    a[1] = As[(ty * 2 + 1) * (KC + 1) + kk];
                    float4 b0 = *(const float4*)&Bs[kk * 128 + tx * 8];
                    float4 b1 = *(const float4*)&Bs[kk * 128 + tx * 8 + 4];
#pragma unroll
                    for (int mm = 0; mm < 2; mm++) {
                        acc[mm][0] += a[mm] * b0.x; acc[mm][1] += a[mm] * b0.y;
                        acc[mm][2] += a[mm] * b0.z; acc[mm][3] += a[mm] * b0.w;
                        acc[mm][4] += a[mm] * b1.x; acc[mm][5] += a[mm] * b1.y;
                        acc[mm][6] += a[mm] * b1.z; acc[mm][7] += a[mm] * b1.w;
                    }
                }
                __syncthreads();
            }
#pragma unroll
            for (int mm = 0; mm < 2; mm++)
#pragma unroll
                for (int nn = 0; nn < 8; nn++) {
                    int n = tx * 8 + nn;
                    g_h[(size_t)(m0 + ty * 2 + mm) * HDIM + n] = fmaxf(acc[mm][nn] + bm2[n], 0.f);
                }
        }
        grid_bar(base + ++bc);
    }

    // final: copy h to output
    for (int i = bx * 256 + tid; i < BATCH * HDIM; i += NCTA * 256)
        out[(size_t)TSTEPS * BATCH * 2 + i] = g_h[i];
}

// ---------------- launch ----------------
extern "C" void kernel_launch(void* const* d_in, const int* in_sizes, int n_in,
                              void* d_out, int out_size) {
    const float* last_pos     = (const float*)d_in[0];
    const float* last_pos_rel = (const float*)d_in[1];
    const float* h0   = (const float*)d_in[2];
    const float* c0   = (const float*)d_in[3];
    /* d_in[4] = seq_start_end (uniform scenes; unused) */
    const float* W_se = (const float*)d_in[5];
    const float* b_se = (const float*)d_in[6];
    const float* W_ih = (const float*)d_in[7];
    const float* b_ih = (const float*)d_in[8];
    const float* W_hh = (const float*)d_in[9];
    const float* b_hh = (const float*)d_in[10];
    const float* W_hp = (const float*)d_in[11];
    const float* b_hp = (const float*)d_in[12];
    const float* W_pse = (const float*)d_in[13];
    const float* b_pse = (const float*)d_in[14];
    const float* W_p1 = (const float*)d_in[15];
    const float* b_p1 = (const float*)d_in[16];
    const float* W_p2 = (const float*)d_in[17];
    const float* b_p2 = (const float*)d_in[18];
    const float* W_m1 = (const float*)d_in[19];
    const float* b_m1 = (const float*)d_in[20];
    const float* W_m2 = (const float*)d_in[21];
    const float* b_m2 = (const float*)d_in[22];
    float* out = (float*)d_out;

    cudaFuncSetAttribute(decoder_persistent, cudaFuncAttributeMaxDynamicSharedMemorySize, SMEM_GP);

    setup_kernel<<<96, 256>>>(last_pos, last_pos_rel, h0, c0, W_se, b_se, W_pse, b_pse,
                              W_p1, b_p1, W_p2, W_m1);
    decoder_persistent<<<NCTA, 256, SMEM_GP>>>(W_ih, b_ih, W_hh, b_hh, W_hp, b_hp,
                                               W_se, b_se, W_p1, b_p2, b_m1, W_m2, b_m2, out);
}

// round 10
// speedup vs baseline: 1.4997x; 1.3118x over previous
#include <cuda_runtime.h>
#include <cuda_fp16.h>
#include <math.h>
#include <stdint.h>

#define BATCH 768
#define NS 32
#define NP 24
#define EDIM 64
#define HDIM 128
#define G4 512      // 4*HDIM
#define P1D 512     // pool hidden
#define BNK 1024
#define MLPD 1024
#define KTOT (HDIM + BNK)   // 1152
#define TSTEPS 12
#define NCTA 144

// ---------------- scratch (static device memory; no allocations) ----------------
__device__ float g_pos[BATCH * 2];
__device__ float g_decin[BATCH * EDIM];
__device__ float g_h[BATCH * HDIM];
__device__ float g_c[BATCH * HDIM];
__device__ float g_hmid[BATCH * HDIM];
__device__ float g_hterm[BATCH * P1D];
__device__ float g_pool[(size_t)BATCH * BNK];
__device__ float g_dh[(size_t)BATCH * MLPD];
__device__ float g_M2[2 * P1D];
__device__ float g_cb[P1D];
__device__ __half g_Wp2t[(size_t)BNK * P1D];       // W_p2^T fp16
__device__ __half g_Wm1t[(size_t)MLPD * KTOT];     // W_m1^T fp16
__device__ unsigned g_bar_count;
__device__ unsigned g_bar_sense;

__device__ __forceinline__ float sigf(float x) { return 1.f / (1.f + expf(-x)); }

__device__ __forceinline__ void mma_f16(float* d, const uint32_t* a, const uint32_t* b) {
    asm volatile(
        "mma.sync.aligned.m16n8k16.row.col.f32.f16.f16.f32 "
        "{%0,%1,%2,%3}, {%4,%5,%6,%7}, {%8,%9}, {%0,%1,%2,%3};"
        : "+f"(d[0]), "+f"(d[1]), "+f"(d[2]), "+f"(d[3])
        : "r"(a[0]), "r"(a[1]), "r"(a[2]), "r"(a[3]), "r"(b[0]), "r"(b[1]));
}

__device__ __forceinline__ void ldsm_x4(uint32_t* r, uint32_t saddr) {
    asm volatile("ldmatrix.sync.aligned.m8n8.x4.shared.b16 {%0,%1,%2,%3}, [%4];"
                 : "=r"(r[0]), "=r"(r[1]), "=r"(r[2]), "=r"(r[3]) : "r"(saddr));
}

__device__ __forceinline__ uint32_t smem_u32(const void* p) {
    uint32_t a;
    asm("{ .reg .u64 t; cvta.to.shared.u64 t, %1; cvt.u32.u64 %0, t; }" : "=r"(a) : "l"(p));
    return a;
}
__device__ __forceinline__ void cp_async16(uint32_t saddr, const void* g) {
    asm volatile("cp.async.cg.shared.global [%0], [%1], 16;" :: "r"(saddr), "l"(g));
}
#define CP_COMMIT() asm volatile("cp.async.commit_group;" ::: "memory")
#define CP_WAIT(n)  asm volatile("cp.async.wait_group %0;" :: "n"(n) : "memory")

// ---- software grid barrier (all NCTA CTAs resident by construction) ----
__device__ __forceinline__ void grid_bar(unsigned target) {
    __syncthreads();
    if (threadIdx.x == 0) {
        __threadfence();
        unsigned old = atomicAdd(&g_bar_count, 1);
        if (old == NCTA - 1) {
            g_bar_count = 0;
            __threadfence();
            atomicAdd(&g_bar_sense, 1);
        } else {
            while ((int)(*(volatile unsigned*)&g_bar_sense - target) < 0)
                __nanosleep(64);
        }
        __threadfence();
    }
    __syncthreads();
}

// ---------------- setup ----------------
__global__ void setup_kernel(const float* __restrict__ last_pos,
                             const float* __restrict__ last_pos_rel,
                             const float* __restrict__ h0, const float* __restrict__ c0,
                             const float* __restrict__ W_se, const float* __restrict__ b_se,
                             const float* __restrict__ W_pse, const float* __restrict__ b_pse,
                             const float* __restrict__ W_p1, const float* __restrict__ b_p1,
                             const float* __restrict__ W_p2, const float* __restrict__ W_m1) {
    int tid = blockIdx.x * blockDim.x + threadIdx.x;
    int nt = gridDim.x * blockDim.x;
    for (int i = tid; i < BATCH * 2; i += nt) g_pos[i] = last_pos[i];
    for (int i = tid; i < BATCH * HDIM; i += nt) { g_h[i] = h0[i]; g_c[i] = c0[i]; }
    for (int i = tid; i < BATCH * EDIM; i += nt) {
        int b = i >> 6, e = i & 63;
        g_decin[i] = b_se[e] + last_pos_rel[b * 2] * W_se[e] + last_pos_rel[b * 2 + 1] * W_se[EDIM + e];
    }
    for (int i = tid; i < 2 * P1D; i += nt) {
        int d = i >> 9, t = i & 511;
        float a = 0.f;
        for (int e = 0; e < EDIM; e++) a += W_pse[d * EDIM + e] * W_p1[e * P1D + t];
        g_M2[i] = a;
    }
    for (int i = tid; i < P1D; i += nt) {
        float a = b_p1[i];
        for (int e = 0; e < EDIM; e++) a += b_pse[e] * W_p1[e * P1D + i];
        g_cb[i] = a;
    }
    for (int i = tid; i < BNK * P1D; i += nt) {
        int n = i / P1D, k = i % P1D;
        g_Wp2t[i] = __float2half_rn(W_p2[(size_t)k * BNK + n]);
    }
    for (int i = tid; i < MLPD * KTOT; i += nt) {
        int n = i / KTOT, k = i % KTOT;
        g_Wm1t[i] = __float2half_rn(W_m1[(size_t)k * MLPD + n]);
    }
}

// ---------------- persistent all-steps kernel ----------------
#define SMB_A 0
#define SMB_B 131072
#define SMB_D 163840
#define SMEM_GP (163840 + 128 * 136 * 2)   // 198656
#define DP 136
#define GP_KC 64
#define KP 72

__global__ __launch_bounds__(256) void decoder_persistent(
    const float* __restrict__ W_ih, const float* __restrict__ b_ih,
    const float* __restrict__ W_hh, const float* __restrict__ b_hh,
    const float* __restrict__ W_hp, const float* __restrict__ b_hp,
    const float* __restrict__ W_se, const float* __restrict__ b_se,
    const float* __restrict__ W_p1,
    const float* __restrict__ bp2, const float* __restrict__ bm1,
    const float* __restrict__ Wm2, const float* __restrict__ bm2,
    float* __restrict__ out) {
    extern __shared__ char smraw[];
    const int tid = threadIdx.x;
    const int bx = blockIdx.x;
    const int wid = tid >> 5, lane = tid & 31;
    const int gid = lane >> 2, tig = lane & 3;
    const int q = lane >> 3;
    const int mrow = (q & 1) * 8 + (lane & 7);
    const int mkof = (q >> 1) * 8;
    const uint32_t swz = (uint32_t)(lane & 7) << 4;
    const uint32_t sb = smem_u32(smraw);

    unsigned base = *(volatile unsigned*)&g_bar_sense;
    unsigned bc = 0;

    for (int t = 0; t < TSTEPS; t++) {
        // ===== phase A: [mlp2 of prev dh ->] h, LSTM, hidden2pos, pos, dec_in, hterm ====
        if (bx < 128) {
            const int row0 = bx * 6;
            float* s_dh = (float*)smraw;             // 6*1024
            float* s_h = s_dh + 6 * MLPD;            // 6*128
            float* s_x = s_h + 6 * HDIM;             // 6*64
            float* s_g = s_x + 6 * EDIM;             // 6*512
            float* s_rel = s_g + 6 * G4;             // 12
            // zero pool rows (atomicMax targets for this step's phase B)
            {
                float4 z = make_float4(0.f, 0.f, 0.f, 0.f);
                float4* pz = (float4*)(g_pool + (size_t)row0 * BNK);
                for (int i = tid; i < 6 * BNK / 4; i += 256) pz[i] = z;
            }
            if (t == 0) {
                for (int i = tid; i < 6 * HDIM; i += 256) s_h[i] = g_h[row0 * HDIM + i];
            } else {
                // mlp2 for own 6 rows: h = relu(dh @ W_m2 + b_m2)
                const float4* src = (const float4*)(g_dh + (size_t)row0 * MLPD);
                float4* dst = (float4*)s_dh;
                for (int i = tid; i < 6 * MLPD / 4; i += 256) dst[i] = src[i];
                __syncthreads();
                int n = tid & 127, rg = tid >> 7;     // rg in {0,1}: rows rg*3..rg*3+2
                float bb = bm2[n];
                float a0 = bb, a1 = bb, a2 = bb;
                const float* d0 = s_dh + (rg * 3 + 0) * MLPD;
                const float* d1 = s_dh + (rg * 3 + 1) * MLPD;
                const float* d2 = s_dh + (rg * 3 + 2) * MLPD;
#pragma unroll 4
                for (int k = 0; k < MLPD; k++) {
                    float w = Wm2[k * HDIM + n];
                    a0 += d0[k] * w; a1 += d1[k] * w; a2 += d2[k] * w;
                }
                s_h[(rg * 3 + 0) * HDIM + n] = fmaxf(a0, 0.f);
                s_h[(rg * 3 + 1) * HDIM + n] = fmaxf(a1, 0.f);
                s_h[(rg * 3 + 2) * HDIM + n] = fmaxf(a2, 0.f);
            }
            for (int i = tid; i < 6 * EDIM; i += 256) s_x[i] = g_decin[row0 * EDIM + i];
            __syncthreads();
            // LSTM gates
            {
                float a0[6], a1[6];
                float bb0 = b_ih[tid] + b_hh[tid];
                float bb1 = b_ih[tid + 256] + b_hh[tid + 256];
#pragma unroll
                for (int r = 0; r < 6; r++) { a0[r] = bb0; a1[r] = bb1; }
                for (int k = 0; k < EDIM; k++) {
                    float w0 = W_ih[k * G4 + tid], w1 = W_ih[k * G4 + tid + 256];
#pragma unroll
                    for (int r = 0; r < 6; r++) {
                        float xa = s_x[r * EDIM + k];
                        a0[r] += w0 * xa; a1[r] += w1 * xa;
                    }
                }
                for (int k = 0; k < HDIM; k++) {
                    float w0 = W_hh[k * G4 + tid], w1 = W_hh[k * G4 + tid + 256];
#pragma unroll
                    for (int r = 0; r < 6; r++) {
                        float ha = s_h[r * HDIM + k];
                        a0[r] += w0 * ha; a1[r] += w1 * ha;
                    }
                }
#pragma unroll
                for (int r = 0; r < 6; r++) {
                    s_g[r * G4 + tid] = a0[r];
                    s_g[r * G4 + tid + 256] = a1[r];
                }
            }
            __syncthreads();
            for (int i = tid; i < 6 * HDIM; i += 256) {
                int r = i >> 7, hc = i & 127;
                const float* gr = s_g + r * G4;
                float ig = sigf(gr[hc]);
                float fg = sigf(gr[HDIM + hc]);
                float gg = tanhf(gr[2 * HDIM + hc]);
                float og = sigf(gr[3 * HDIM + hc]);
                float c = fg * g_c[(row0 + r) * HDIM + hc] + ig * gg;
                float hn = og * tanhf(c);
                g_c[(row0 + r) * HDIM + hc] = c;
                g_hmid[(row0 + r) * HDIM + hc] = hn;
                s_h[r * HDIM + hc] = hn;
            }
            __syncthreads();
            if (tid < 12) {
                int r = tid >> 1, d = tid & 1;
                float a = b_hp[d];
                for (int k = 0; k < HDIM; k++) a += s_h[r * HDIM + k] * W_hp[k * 2 + d];
                s_rel[tid] = a;
                out[(size_t)t * BATCH * 2 + row0 * 2 + tid] = a;
                g_pos[row0 * 2 + tid] = a + g_pos[row0 * 2 + tid];
            }
            __syncthreads();
            for (int i = tid; i < 6 * EDIM; i += 256) {
                int r = i >> 6, e = i & 63;
                g_decin[(row0 + r) * EDIM + e] =
                    b_se[e] + s_rel[r * 2] * W_se[e] + s_rel[r * 2 + 1] * W_se[EDIM + e];
            }
            // hterm
            {
                float a0[6], a1[6];
                float cb0 = g_cb[tid], cb1 = g_cb[tid + 256];
#pragma unroll
                for (int r = 0; r < 6; r++) { a0[r] = cb0; a1[r] = cb1; }
                for (int k = 0; k < HDIM; k++) {
                    float w0 = W_p1[(EDIM + k) * P1D + tid];
                    float w1 = W_p1[(EDIM + k) * P1D + tid + 256];
#pragma unroll
                    for (int r = 0; r < 6; r++) {
                        float ha = s_h[r * HDIM + k];
                        a0[r] += w0 * ha; a1[r] += w1 * ha;
                    }
                }
#pragma unroll
                for (int r = 0; r < 6; r++) {
                    g_hterm[(row0 + r) * P1D + tid] = a0[r];
                    g_hterm[(row0 + r) * P1D + tid + 256] = a1[r];
                }
            }
        }
        grid_bar(base + ++bc);

        // ================= phase B: fused layer1 + GEMM + pool ========================
        {
            const uint32_t sbA = sb + SMB_A;
            const uint32_t sbB = sb + SMB_B;
            __half* Dsm = (__half*)(smraw + SMB_D);
            float* sdx = (float*)(smraw + SMB_D);
            float* sdy = sdx + 128;
            int* sjr = (int*)(sdy + 128);
            float* sm0 = (float*)(sjr + 128);
            float* sm1 = sm0 + 512;
            const int wm = (wid & 1) * 64, wn = (wid >> 1) * 32;
            const int R0 = bx * 128;

            // prefetch B chunk 0 FIRST (overlaps the A fill below)
#pragma unroll
            for (int p = 0; p < 4; p++) {
                int idx = tid + p * 256;
                int row = idx >> 3, seg = idx & 7;
                uint32_t dst = sbB + (uint32_t)row * 128 +
                               (((uint32_t)seg * 16) ^ ((uint32_t)(row & 7) << 4));
                cp_async16(dst, g_Wp2t + (size_t)row * P1D + seg * 8);
            }
            CP_COMMIT();

            if (tid < 128) {
                int gr = R0 + tid;
                int s = gr / 576;
                int rem = gr - s * 576;
                int i = rem / 24;
                int j = rem - i * 24;
                int jped = s * 24 + j, iped = s * 24 + i;
                sjr[tid] = jped;
                sdx[tid] = g_pos[jped * 2] - g_pos[iped * 2];
                sdy[tid] = g_pos[jped * 2 + 1] - g_pos[iped * 2 + 1];
            }
            for (int k = tid; k < P1D; k += 256) { sm0[k] = g_M2[k]; sm1[k] = g_M2[P1D + k]; }
            __syncthreads();

            for (int p = 0; p < 32; p++) {
                int idx = tid + p * 256;
                int r = idx >> 6, sg = idx & 63;
                int k0 = sg * 8;
                const float4* hp = (const float4*)(g_hterm + (size_t)sjr[r] * P1D + k0);
                float4 h0 = hp[0], h1 = hp[1];
                float dx = sdx[r], dy = sdy[r];
                float4 a0 = *(const float4*)(sm0 + k0), a1 = *(const float4*)(sm0 + k0 + 4);
                float4 c0 = *(const float4*)(sm1 + k0), c1 = *(const float4*)(sm1 + k0 + 4);
                __half2 o[4];
                o[0] = __floats2half2_rn(fmaxf(h0.x + dx * a0.x + dy * c0.x, 0.f),
                                         fmaxf(h0.y + dx * a0.y + dy * c0.y, 0.f));
                o[1] = __floats2half2_rn(fmaxf(h0.z + dx * a0.z + dy * c0.z, 0.f),
                                         fmaxf(h0.w + dx * a0.w + dy * c0.w, 0.f));
                o[2] = __floats2half2_rn(fmaxf(h1.x + dx * a1.x + dy * c1.x, 0.f),
                                         fmaxf(h1.y + dx * a1.y + dy * c1.y, 0.f));
                o[3] = __floats2half2_rn(fmaxf(h1.z + dx * a1.z + dy * c1.z, 0.f),
                                         fmaxf(h1.w + dx * a1.w + dy * c1.w, 0.f));
                uint32_t off = (uint32_t)r * 1024 + (((uint32_t)sg * 16) ^ ((uint32_t)(r & 7) << 4));
                *(uint4*)(smraw + SMB_A + off) = *(uint4*)o;
            }
            __syncthreads();

            int buf = 0;
            for (int nt = 0; nt < 8; nt++) {
                float acc[4][4][4] = {};
                for (int ck = 0; ck < 8; ck++) {
                    const int c = nt * 8 + ck + 1;
                    if (c < 64) {
                        const int nnt = c >> 3, nck = c & 7;
                        const __half* src = g_Wp2t + (size_t)nnt * 128 * P1D + nck * 64;
                        uint32_t dstb = sbB + (uint32_t)(buf ^ 1) * 16384;
#pragma unroll
                        for (int p = 0; p < 4; p++) {
                            int idx = tid + p * 256;
                            int row = idx >> 3, seg = idx & 7;
                            cp_async16(dstb + (uint32_t)row * 128 +
                                           (((uint32_t)seg * 16) ^ ((uint32_t)(row & 7) << 4)),
                                       src + (size_t)row * P1D + seg * 8);
                        }
                        CP_COMMIT();
                        CP_WAIT(1);
                    } else {
                        CP_WAIT(0);
                    }
                    __syncthreads();
                    const uint32_t sBc = sbB + (uint32_t)buf * 16384;
                    const uint32_t kbase = (uint32_t)(ck * 64 + mkof) * 2;
#pragma unroll
                    for (int kk = 0; kk < 64; kk += 16) {
                        const uint32_t kbA = kbase + (uint32_t)kk * 2;
                        const uint32_t kbB = (uint32_t)(kk + mkof) * 2;
                        uint32_t af[4][4], bf[4][2];
#pragma unroll
                        for (int mi = 0; mi < 4; mi++) {
                            uint32_t addr = sbA + (uint32_t)(wm + mi * 16 + mrow) * 1024 + (kbA ^ swz);
                            ldsm_x4(af[mi], addr);
                        }
#pragma unroll
                        for (int pi = 0; pi < 2; pi++) {
                            uint32_t r[4];
                            uint32_t addr = sBc + (uint32_t)(wn + pi * 16 + mrow) * 128 + (kbB ^ swz);
                            ldsm_x4(r, addr);
                            bf[2 * pi][0] = r[0]; bf[2 * pi][1] = r[2];
                            bf[2 * pi + 1][0] = r[1]; bf[2 * pi + 1][1] = r[3];
                        }
#pragma unroll
                        for (int mi = 0; mi < 4; mi++)
#pragma unroll
                            for (int ni = 0; ni < 4; ni++)
                                mma_f16(acc[mi][ni], af[mi], bf[ni]);
                    }
                    __syncthreads();
                    buf ^= 1;
                }
                const int n0 = nt * 128;
#pragma unroll
                for (int mi = 0; mi < 4; mi++)
#pragma unroll
                    for (int ni = 0; ni < 4; ni++) {
                        int r = wm + mi * 16 + gid;
                        int col = wn + ni * 8 + 2 * tig;
                        float bv0 = bp2[n0 + col], bv1 = bp2[n0 + col + 1];
                        *(__half2*)(Dsm + r * DP + col) =
                            __floats2half2_rn(fmaxf(acc[mi][ni][0] + bv0, 0.f),
                                              fmaxf(acc[mi][ni][1] + bv1, 0.f));
                        *(__half2*)(Dsm + (r + 8) * DP + col) =
                            __floats2half2_rn(fmaxf(acc[mi][ni][2] + bv0, 0.f),
                                              fmaxf(acc[mi][ni][3] + bv1, 0.f));
                    }
                __syncthreads();
                const int ped0 = R0 / NP;
                const int pedN = (R0 + 127) / NP - ped0 + 1;
                for (int it = tid; it < pedN * 128; it += 256) {
                    int pl = it >> 7, col = it & 127;
                    int gp = ped0 + pl;
                    int rs = gp * NP - R0, re = rs + NP;
                    if (rs < 0) rs = 0;
                    if (re > 128) re = 128;
                    float v = 0.f;
                    for (int rr = rs; rr < re; rr++) v = fmaxf(v, __half2float(Dsm[rr * DP + col]));
                    atomicMax((int*)&g_pool[(size_t)gp * BNK + n0 + col], __float_as_int(v));
                }
                __syncthreads();
            }
        }
        grid_bar(base + ++bc);

        // ================= phase C: mlp1 (fp16 mma, double-buffered B) ================
        if (bx < 96) {
            __half* As = (__half*)smraw;               // 64*KP
            __half* Bs = As + 64 * KP;                 // 2 x 128*KP
            const uint32_t sbA = smem_u32(As);
            const uint32_t sbB = smem_u32(Bs);
            const int wm = (wid & 1) * 32, wn = (wid >> 1) * 32;
            const int n0 = (bx & 7) * 128, m0 = (bx >> 3) * 64;
            const __half* Bg = g_Wm1t + (size_t)n0 * KTOT;
            const int lrow = tid >> 3;
            const int lcol = (tid & 7) * 8;
            const uint32_t bstage = 128 * KP * 2;      // bytes per B stage

            // prefetch B chunk 0
#pragma unroll
            for (int p = 0; p < 4; p++) {
                int row = lrow + p * 32;
                cp_async16(sbB + (uint32_t)(row * KP + lcol) * 2,
                           Bg + (size_t)row * KTOT + lcol);
            }
            CP_COMMIT();

            float acc[2][4][4] = {};
            int buf = 0;
            for (int ci = 0; ci < KTOT / GP_KC; ci++) {
                const int kc = ci * GP_KC;
                if (ci + 1 < KTOT / GP_KC) {
                    const int kn = kc + GP_KC;
#pragma unroll
                    for (int p = 0; p < 4; p++) {
                        int row = lrow + p * 32;
                        cp_async16(sbB + (uint32_t)(buf ^ 1) * bstage +
                                       (uint32_t)(row * KP + lcol) * 2,
                                   Bg + (size_t)row * KTOT + kn + lcol);
                    }
                    CP_COMMIT();
                }
                // A: load fp32, convert to fp16 (single-buffered; safe after prev end-sync)
#pragma unroll
                for (int p = 0; p < 2; p++) {
                    int row = lrow + p * 32;
                    int k = kc + lcol;
                    const float* src = (k < HDIM) ? (g_hmid + (size_t)(m0 + row) * HDIM + k)
                                                  : (g_pool + (size_t)(m0 + row) * BNK + (k - HDIM));
                    float4 v0 = ((const float4*)src)[0];
                    float4 v1 = ((const float4*)src)[1];
                    __half2* da = (__half2*)(As + row * KP + lcol);
                    da[0] = __floats2half2_rn(v0.x, v0.y);
                    da[1] = __floats2half2_rn(v0.z, v0.w);
                    da[2] = __floats2half2_rn(v1.x, v1.y);
                    da[3] = __floats2half2_rn(v1.z, v1.w);
                }
                if (ci + 1 < KTOT / GP_KC) { CP_WAIT(1); } else { CP_WAIT(0); }
                __syncthreads();
                const uint32_t sBc = sbB + (uint32_t)buf * bstage;
#pragma unroll
                for (int kk = 0; kk < GP_KC; kk += 16) {
                    uint32_t af[2][4], bf[4][2];
#pragma unroll
                    for (int mi = 0; mi < 2; mi++) {
                        uint32_t addr = sbA + (uint32_t)((wm + mi * 16 + mrow) * KP + kk + mkof) * 2;
                        ldsm_x4(af[mi], addr);
                    }
#pragma unroll
                    for (int pi = 0; pi < 2; pi++) {
                        uint32_t r[4];
                        uint32_t addr = sBc + (uint32_t)((wn + pi * 16 + mrow) * KP + kk + mkof) * 2;
                        ldsm_x4(r, addr);
                        bf[2 * pi][0] = r[0]; bf[2 * pi][1] = r[2];
                        bf[2 * pi + 1][0] = r[1]; bf[2 * pi + 1][1] = r[3];
                    }
#pragma unroll
                    for (int mi = 0; mi < 2; mi++)
#pragma unroll
                        for (int ni = 0; ni < 4; ni++)
                            mma_f16(acc[mi][ni], af[mi], bf[ni]);
                }
                __syncthreads();
                buf ^= 1;
            }
#pragma unroll
            for (int mi = 0; mi < 2; mi++)
#pragma unroll
                for (int ni = 0; ni < 4; ni++) {
                    int r = m0 + wm + mi * 16 + gid;
                    int c = n0 + wn + ni * 8 + 2 * tig;
                    float bv0 = bm1[c], bv1 = bm1[c + 1];
                    g_dh[(size_t)r * MLPD + c]           = fmaxf(acc[mi][ni][0] + bv0, 0.f);
                    g_dh[(size_t)r * MLPD + c + 1]       = fmaxf(acc[mi][ni][1] + bv1, 0.f);
                    g_dh[(size_t)(r + 8) * MLPD + c]     = fmaxf(acc[mi][ni][2] + bv0, 0.f);
                    g_dh[(size_t)(r + 8) * MLPD + c + 1] = fmaxf(acc[mi][ni][3] + bv1, 0.f);
                }
        }
        grid_bar(base + ++bc);
    }

    // ===== final: mlp2 of step-12 dh -> h_fin, written straight to out ===============
    if (bx < 128) {
        const int row0 = bx * 6;
        float* s_dh = (float*)smraw;
        const float4* src = (const float4*)(g_dh + (size_t)row0 * MLPD);
        float4* dst = (float4*)s_dh;
        for (int i = tid; i < 6 * MLPD / 4; i += 256) dst[i] = src[i];
        __syncthreads();
        int n = tid & 127, rg = tid >> 7;
        float bb = bm2[n];
        float a0 = bb, a1 = bb, a2 = bb;
        const float* d0 = s_dh + (rg * 3 + 0) * MLPD;
        const float* d1 = s_dh + (rg * 3 + 1) * MLPD;
        const float* d2 = s_dh + (rg * 3 + 2) * MLPD;
#pragma unroll 4
        for (int k = 0; k < MLPD; k++) {
            float w = Wm2[k * HDIM + n];
            a0 += d0[k] * w; a1 += d1[k] * w; a2 += d2[k] * w;
        }
        float* ob = out + (size_t)TSTEPS * BATCH * 2;
        ob[(row0 + rg * 3 + 0) * HDIM + n] = fmaxf(a0, 0.f);
        ob[(row0 + rg * 3 + 1) * HDIM + n] = fmaxf(a1, 0.f);
        ob[(row0 + rg * 3 + 2) * HDIM + n] = fmaxf(a2, 0.f);
    }
}

// ---------------- launch ----------------
extern "C" void kernel_launch(void* const* d_in, const int* in_sizes, int n_in,
                              void* d_out, int out_size) {
    const float* last_pos     = (const float*)d_in[0];
    const float* last_pos_rel = (const float*)d_in[1];
    const float* h0   = (const float*)d_in[2];
    const float* c0   = (const float*)d_in[3];
    /* d_in[4] = seq_start_end (uniform scenes; unused) */
    const float* W_se = (const float*)d_in[5];
    const float* b_se = (const float*)d_in[6];
    const float* W_ih = (const float*)d_in[7];
    const float* b_ih = (const float*)d_in[8];
    const float* W_hh = (const float*)d_in[9];
    const float* b_hh = (const float*)d_in[10];
    const float* W_hp = (const float*)d_in[11];
    const float* b_hp = (const float*)d_in[12];
    const float* W_pse = (const float*)d_in[13];
    const float* b_pse = (const float*)d_in[14];
    const float* W_p1 = (const float*)d_in[15];
    const float* b_p1 = (const float*)d_in[16];
    const float* W_p2 = (const float*)d_in[17];
    const float* b_p2 = (const float*)d_in[18];
    const float* W_m1 = (const float*)d_in[19];
    const float* b_m1 = (const float*)d_in[20];
    const float* W_m2 = (const float*)d_in[21];
    const float* b_m2 = (const float*)d_in[22];
    float* out = (float*)d_out;

    cudaFuncSetAttribute(decoder_persistent, cudaFuncAttributeMaxDynamicSharedMemorySize, SMEM_GP);

    setup_kernel<<<96, 256>>>(last_pos, last_pos_rel, h0, c0, W_se, b_se, W_pse, b_pse,
                              W_p1, b_p1, W_p2, W_m1);
    decoder_persistent<<<NCTA, 256, SMEM_GP>>>(W_ih, b_ih, W_hh, b_hh, W_hp, b_hp,
                                               W_se, b_se, W_p1, b_p2, b_m1, W_m2, b_m2, out);
}